// round 3
// baseline (speedup 1.0000x reference)
#include <cuda_runtime.h>
#include <cstdint>

#define S_LEN 2048
#define E_DIM 1024
#define NH    16
#define HD    64
#define WWIN  128
#define BATCH 2
#define M_TOT (BATCH * S_LEN)   // 4096

// ---------------- scratch (device globals; no allocations allowed) ----------------
__device__ float g_Q[M_TOT * E_DIM];
__device__ float g_K[M_TOT * E_DIM];
__device__ float g_V[M_TOT * E_DIM];
__device__ float g_Vtot[BATCH * NH * HD];

// ---------------- packed f32x2 helpers (Blackwell FFMA2 path) ----------------
__device__ __forceinline__ unsigned long long pk2(float x, float y) {
    unsigned long long r;
    asm("mov.b64 %0, {%1, %2};" : "=l"(r) : "f"(x), "f"(y));
    return r;
}
__device__ __forceinline__ float2 upk2(unsigned long long v) {
    float2 r;
    asm("mov.b64 {%0, %1}, %2;" : "=f"(r.x), "=f"(r.y) : "l"(v));
    return r;
}
__device__ __forceinline__ unsigned long long ffma2(unsigned long long a,
                                                    unsigned long long b,
                                                    unsigned long long c) {
    unsigned long long d;
    asm("fma.rn.f32x2 %0, %1, %2, %3;" : "=l"(d) : "l"(a), "l"(b), "l"(c));
    return d;
}

// ============================================================================
// Kernel 1: fused QKV projection GEMM.
// Out[m,n] = sum_k X[m,k] * W[n,k] + bias[n]   (torch Linear: x @ W.T + b)
// BM=BN=128, BK=8, 256 threads, 8x8 micro-tile, double-buffered smem,
// accumulators packed along n into f32x2 pairs -> FFMA2 (2x fp32 rate).
// grid = (N/128=8, M/128=32, 3)  z selects Q/K/V.
// ============================================================================
__global__ __launch_bounds__(256, 1)
void qkv_gemm_kernel(const float* __restrict__ X,
                     const float* __restrict__ Wq, const float* __restrict__ bq,
                     const float* __restrict__ Wk, const float* __restrict__ bk,
                     const float* __restrict__ Wv, const float* __restrict__ bv) {
    const float* W;
    const float* bias;
    float* Out;
    const int z = blockIdx.z;
    if (z == 0)      { W = Wq; bias = bq; Out = g_Q; }
    else if (z == 1) { W = Wk; bias = bk; Out = g_K; }
    else             { W = Wv; bias = bv; Out = g_V; }

    __shared__ float As[2][8][128];
    __shared__ float Bs[2][8][128];

    const int tid  = threadIdx.x;
    const int m0   = blockIdx.y * 128;
    const int n0   = blockIdx.x * 128;
    const int lrow = tid >> 1;            // 0..127
    const int lcol = (tid & 1) * 4;       // 0 or 4
    const float* Ap = X + (size_t)(m0 + lrow) * E_DIM + lcol;
    const float* Bp = W + (size_t)(n0 + lrow) * E_DIM + lcol;
    const int tx = tid & 15;
    const int ty = tid >> 4;

    // prologue: load tile 0
    {
        float4 a4 = *(const float4*)Ap;
        float4 b4 = *(const float4*)Bp;
        As[0][lcol + 0][lrow] = a4.x; As[0][lcol + 1][lrow] = a4.y;
        As[0][lcol + 2][lrow] = a4.z; As[0][lcol + 3][lrow] = a4.w;
        Bs[0][lcol + 0][lrow] = b4.x; Bs[0][lcol + 1][lrow] = b4.y;
        Bs[0][lcol + 2][lrow] = b4.z; Bs[0][lcol + 3][lrow] = b4.w;
    }
    __syncthreads();

    unsigned long long acc[8][4];
#pragma unroll
    for (int m = 0; m < 8; m++)
#pragma unroll
        for (int n = 0; n < 4; n++) acc[m][n] = 0ULL;

    float4 na = make_float4(0.f, 0.f, 0.f, 0.f);
    float4 nb = make_float4(0.f, 0.f, 0.f, 0.f);
    int buf = 0;
    for (int kt = 0; kt < 128; ++kt) {
        if (kt < 127) {
            na = *(const float4*)(Ap + (kt + 1) * 8);
            nb = *(const float4*)(Bp + (kt + 1) * 8);
        }
#pragma unroll
        for (int k = 0; k < 8; ++k) {
            float4 a0 = *(const float4*)&As[buf][k][ty * 4];
            float4 a1 = *(const float4*)&As[buf][k][ty * 4 + 64];
            float4 b0 = *(const float4*)&Bs[buf][k][tx * 4];
            float4 b1 = *(const float4*)&Bs[buf][k][tx * 4 + 64];
            unsigned long long bp[4] = { pk2(b0.x, b0.y), pk2(b0.z, b0.w),
                                         pk2(b1.x, b1.y), pk2(b1.z, b1.w) };
            float am[8] = { a0.x, a0.y, a0.z, a0.w, a1.x, a1.y, a1.z, a1.w };
#pragma unroll
            for (int m = 0; m < 8; m++) {
                unsigned long long ad = pk2(am[m], am[m]);
#pragma unroll
                for (int n = 0; n < 4; n++) acc[m][n] = ffma2(ad, bp[n], acc[m][n]);
            }
        }
        if (kt < 127) {
            buf ^= 1;
            As[buf][lcol + 0][lrow] = na.x; As[buf][lcol + 1][lrow] = na.y;
            As[buf][lcol + 2][lrow] = na.z; As[buf][lcol + 3][lrow] = na.w;
            Bs[buf][lcol + 0][lrow] = nb.x; Bs[buf][lcol + 1][lrow] = nb.y;
            Bs[buf][lcol + 2][lrow] = nb.z; Bs[buf][lcol + 3][lrow] = nb.w;
            __syncthreads();
        }
    }

    // epilogue: unpack, add bias, store
    const float4 bl0 = *(const float4*)&bias[n0 + tx * 4];
    const float4 bl1 = *(const float4*)&bias[n0 + 64 + tx * 4];
#pragma unroll
    for (int m = 0; m < 8; m++) {
        const int grow = m0 + ((m < 4) ? (ty * 4 + m) : (64 + ty * 4 + (m - 4)));
        float2 p0 = upk2(acc[m][0]);
        float2 p1 = upk2(acc[m][1]);
        float2 p2 = upk2(acc[m][2]);
        float2 p3 = upk2(acc[m][3]);
        float4 o0 = make_float4(p0.x + bl0.x, p0.y + bl0.y, p1.x + bl0.z, p1.y + bl0.w);
        float4 o1 = make_float4(p2.x + bl1.x, p2.y + bl1.y, p3.x + bl1.z, p3.y + bl1.w);
        *(float4*)&Out[(size_t)grow * E_DIM + n0 + tx * 4]      = o0;
        *(float4*)&Out[(size_t)grow * E_DIM + n0 + 64 + tx * 4] = o1;
    }
}

// ============================================================================
// Kernel 2: V_total[b,h,d] = sum over all 2048 keys of v[b,h,j,d]
//   = sum over 128 rows of the head's slab, folded over 16 column blocks.
// grid = B*H = 32 blocks, 512 threads.
// ============================================================================
__global__ __launch_bounds__(512, 1)
void vtotal_kernel() {
    const int bh = blockIdx.x;                          // b*16 + h
    const float* Vb = g_V + (size_t)bh * 128 * E_DIM;   // head slab base
    const int tid = threadIdx.x;
    const int d = tid & 63;
    const int g = tid >> 6;                             // 0..7
    float s = 0.f;
    for (int r = g; r < 128; r += 8) {
        const float* row = Vb + (size_t)r * E_DIM;
#pragma unroll
        for (int cb = 0; cb < 16; cb++) s += row[cb * 64 + d];
    }
    __shared__ float red[8][64];
    red[g][d] = s;
    __syncthreads();
    if (tid < 64) {
        float tt = 0.f;
#pragma unroll
        for (int i2 = 0; i2 < 8; i2++) tt += red[i2][tid];
        g_Vtot[bh * 64 + tid] = tt;
    }
}

// ============================================================================
// Kernel 3: windowed attention with zero-padded softmax.
// One block = (b, h, t) where t indexes a 16-query tile (= 1 Q row).
// Keys needed: j in [16(t-8), 16(t-8)+272) -> 17 K/V rows (clipped).
// s_s stores w = exp(score)-1 (0 outside window); denom = S + rowsum(w);
// out = (V_total + sum w*v) / denom.
// grid = (128, 16, 2), 256 threads, ~179 KB dynamic smem (1 CTA/SM).
// ============================================================================
#define KS_STRIDE 321   // 321 % 32 = 1 -> conflict-free transposed K
#define VS_STRIDE 68    // 16B-aligned rows for float4 V access
#define OFF_Q     0
#define OFF_KS    1024
#define OFF_VS    (OFF_KS + 64 * KS_STRIDE)       // 21568
#define OFF_SS    (OFF_VS + 272 * VS_STRIDE)      // 40064
#define OFF_PART  (OFF_SS + 16 * 272)             // 44416
#define OFF_PART2 (OFF_PART + 16 * 64)            // 45440
#define OFF_DEN   (OFF_PART2 + 256)               // 45696
#define OFF_VT    (OFF_DEN + 16)                  // 45712
#define ATTN_SMEM_FLOATS (OFF_VT + 64)            // 45776
#define ATTN_SMEM_BYTES  (ATTN_SMEM_FLOATS * 4)   // 183104

__global__ __launch_bounds__(256, 1)
void attn_kernel(float* __restrict__ out) {
    extern __shared__ float sm[];
    float* q_s   = sm + OFF_Q;
    float* ks    = sm + OFF_KS;    // [64][321] transposed: ks[d][jl]
    float* vs    = sm + OFF_VS;    // [272][68] row-major: vs[jl][d]
    float* s_s   = sm + OFF_SS;    // [16][272] weights
    float* part  = sm + OFF_PART;  // [16][64] rowsum partials
    float* part2 = sm + OFF_PART2; // [16][16]
    float* den   = sm + OFF_DEN;   // [16]
    float* vt    = sm + OFF_VT;    // [64] V_total for this head

    const int t   = blockIdx.x;    // 0..127 (query tile = Q row within head)
    const int h   = blockIdx.y;
    const int b   = blockIdx.z;
    const int tid = threadIdx.x;

    const size_t headbase = ((size_t)b * S_LEN + (size_t)h * 128) * E_DIM;
    const float* Qrow = g_Q + headbase + (size_t)t * E_DIM;
    const float* Kh   = g_K + headbase;
    const float* Vh   = g_V + headbase;

    // ---- load phase ----
    *(float4*)&q_s[tid * 4] = *(const float4*)&Qrow[tid * 4];
    if (tid < 64) vt[tid] = g_Vtot[((b * NH) + h) * HD + tid];

    const int r0 = t - 8;  // first K/V row offset within head
    for (int e4 = tid; e4 < 17 * 256; e4 += 256) {
        const int rro = e4 >> 8;                // 0..16
        const int c4  = (e4 & 255) << 2;        // column (multiple of 4)
        const int rr  = r0 + rro;
        if (rr >= 0 && rr < 128) {
            float4 kv4 = *(const float4*)(Kh + (size_t)rr * E_DIM + c4);
            float4 vv4 = *(const float4*)(Vh + (size_t)rr * E_DIM + c4);
            const int d0 = c4 & 63;
            const int jl = (rro << 4) + (c4 >> 6);
            ks[(d0 + 0) * KS_STRIDE + jl] = kv4.x;
            ks[(d0 + 1) * KS_STRIDE + jl] = kv4.y;
            ks[(d0 + 2) * KS_STRIDE + jl] = kv4.z;
            ks[(d0 + 3) * KS_STRIDE + jl] = kv4.w;
            *(float4*)&vs[jl * VS_STRIDE + d0] = vv4;
        }
    }
    __syncthreads();

    // ---- score phase: each thread 4 queries x 5 key-strips ----
    const int qb = tid >> 6;   // 0..3 (query group of 4)
    const int kt = tid & 63;
    float accs[4][5];
#pragma unroll
    for (int qq = 0; qq < 4; qq++)
#pragma unroll
        for (int c = 0; c < 5; c++) accs[qq][c] = 0.f;

#pragma unroll 8
    for (int d = 0; d < 64; d++) {
        float kvv[5];
#pragma unroll
        for (int c = 0; c < 5; c++) kvv[c] = ks[d * KS_STRIDE + kt + 64 * c];
#pragma unroll
        for (int qq = 0; qq < 4; qq++) {
            const float qv = q_s[(qb * 4 + qq) * 64 + d];
#pragma unroll
            for (int c = 0; c < 5; c++) accs[qq][c] = fmaf(qv, kvv[c], accs[qq][c]);
        }
    }

    const float scale = 0.125f;  // D^-0.5
#pragma unroll
    for (int qq = 0; qq < 4; qq++) {
        const int qi = qb * 4 + qq;
        const int i  = t * 16 + qi;
        float rp = 0.f;
#pragma unroll
        for (int c = 0; c < 5; c++) {
            const int jl = kt + 64 * c;
            if (jl < 272) {
                const int j = r0 * 16 + jl;
                const bool win = (j >= 0) && (j < S_LEN) && (j >= i - WWIN) && (j < i + WWIN);
                float w = 0.f;
                if (win) w = __expf(accs[qq][c] * scale) - 1.f;
                s_s[qi * 272 + jl] = w;
                rp += w;
            }
        }
        part[qi * 64 + kt] = rp;
    }
    __syncthreads();

    // ---- rowsum reduce -> denom ----
    {
        const int qi = tid >> 4, sg = tid & 15;
        part2[qi * 16 + sg] = part[qi * 64 + sg] + part[qi * 64 + sg + 16] +
                              part[qi * 64 + sg + 32] + part[qi * 64 + sg + 48];
    }
    __syncthreads();
    if (tid < 16) {
        float ssum = 0.f;
#pragma unroll
        for (int sg = 0; sg < 16; sg++) ssum += part2[tid * 16 + sg];
        den[tid] = (float)S_LEN + ssum;
    }

    // ---- PV phase: thread = (jl-partition p, 4 queries, 4 contiguous d) ----
    const int p   = tid >> 6;          // 0..3
    const int qb2 = (tid >> 4) & 3;    // 0..3
    const int dl  = tid & 15;          // 0..15 -> d = dl*4..dl*4+3
    float4 oacc[4];
#pragma unroll
    for (int qq = 0; qq < 4; qq++) oacc[qq] = make_float4(0.f, 0.f, 0.f, 0.f);

    for (int jl = p; jl < 272; jl += 4) {
        const float4 v4 = *(const float4*)&vs[jl * VS_STRIDE + dl * 4];
#pragma unroll
        for (int qq = 0; qq < 4; qq++) {
            const float w = s_s[(qb2 * 4 + qq) * 272 + jl];
            oacc[qq].x = fmaf(w, v4.x, oacc[qq].x);
            oacc[qq].y = fmaf(w, v4.y, oacc[qq].y);
            oacc[qq].z = fmaf(w, v4.z, oacc[qq].z);
            oacc[qq].w = fmaf(w, v4.w, oacc[qq].w);
        }
    }
    float* opart = ks;  // reuse K smem (all ks reads done before last sync)
#pragma unroll
    for (int qq = 0; qq < 4; qq++)
        *(float4*)&opart[(p * 16 + qb2 * 4 + qq) * 64 + dl * 4] = oacc[qq];
    __syncthreads();

    // ---- combine partials + V_total, divide by denom, write out ----
    {
        const int qi = tid >> 4;
        const int dc = tid & 15;
        float4 sum = *(const float4*)&vt[dc * 4];
#pragma unroll
        for (int pp = 0; pp < 4; pp++) {
            const float4 o = *(const float4*)&opart[(pp * 16 + qi) * 64 + dc * 4];
            sum.x += o.x; sum.y += o.y; sum.z += o.z; sum.w += o.w;
        }
        const float inv = 1.0f / den[qi];
        sum.x *= inv; sum.y *= inv; sum.z *= inv; sum.w *= inv;
        const int i = t * 16 + qi;
        *(float4*)&out[((size_t)b * S_LEN + i) * E_DIM + h * HD + dc * 4] = sum;
    }
}

// ============================================================================
// kernel_launch
// ============================================================================
extern "C" void kernel_launch(void* const* d_in, const int* in_sizes, int n_in,
                              void* d_out, int out_size) {
    (void)in_sizes; (void)n_in; (void)out_size;
    const float* x  = (const float*)d_in[0];
    const float* Wq = (const float*)d_in[1];
    const float* bq = (const float*)d_in[2];
    const float* Wk = (const float*)d_in[3];
    const float* bk = (const float*)d_in[4];
    const float* Wv = (const float*)d_in[5];
    const float* bv = (const float*)d_in[6];
    float* out = (float*)d_out;

    dim3 g1(8, 32, 3);  // N-tiles, M-tiles, {Q,K,V}
    qkv_gemm_kernel<<<g1, 256>>>(x, Wq, bq, Wk, bk, Wv, bv);

    vtotal_kernel<<<BATCH * NH, 512>>>();

    cudaFuncSetAttribute(attn_kernel, cudaFuncAttributeMaxDynamicSharedMemorySize,
                         ATTN_SMEM_BYTES);
    dim3 g3(128, NH, BATCH);
    attn_kernel<<<g3, 256, ATTN_SMEM_BYTES>>>(out);
}

// round 5
// speedup vs baseline: 1.3327x; 1.3327x over previous
#include <cuda_runtime.h>
#include <cuda_bf16.h>
#include <cstdint>

#define S_LEN 2048
#define E_DIM 1024
#define NH    16
#define HD    64
#define WWIN  128
#define BATCH 2
#define M_TOT (BATCH * S_LEN)   // 4096

// ---------------- scratch (device globals; no allocations allowed) ----------------
__device__ float g_Q[M_TOT * E_DIM];
__device__ float g_K[M_TOT * E_DIM];
__device__ float g_V[M_TOT * E_DIM];
__device__ float g_Vtot[BATCH * NH * HD];
// bf16 split operands
__device__ __nv_bfloat16 g_Xhi[M_TOT * E_DIM];
__device__ __nv_bfloat16 g_Xlo[M_TOT * E_DIM];
__device__ __nv_bfloat16 g_Whi[3 * E_DIM * E_DIM];
__device__ __nv_bfloat16 g_Wlo[3 * E_DIM * E_DIM];

// ---------------- PTX helpers (baseline ISA only — no sm_103a features) ----------
__device__ __forceinline__ uint32_t smem_u32(const void* p) {
    uint32_t a;
    asm("{ .reg .u64 t; cvta.to.shared.u64 t, %1; cvt.u32.u64 %0, t; }" : "=r"(a) : "l"(p));
    return a;
}
__device__ __forceinline__ void cp_async16(uint32_t s, const void* g) {
    asm volatile("cp.async.cg.shared.global [%0], [%1], 16;" :: "r"(s), "l"(g) : "memory");
}
#define CP_COMMIT() asm volatile("cp.async.commit_group;" ::: "memory")
#define CP_WAIT(n)  asm volatile("cp.async.wait_group %0;" :: "n"(n) : "memory")

__device__ __forceinline__ void ldmx4(uint32_t r[4], uint32_t addr) {
    asm volatile("ldmatrix.sync.aligned.m8n8.x4.shared.b16 {%0,%1,%2,%3}, [%4];"
                 : "=r"(r[0]), "=r"(r[1]), "=r"(r[2]), "=r"(r[3]) : "r"(addr));
}
__device__ __forceinline__ void mma16816(float c[4], const uint32_t a[4],
                                         uint32_t b0, uint32_t b1) {
    asm volatile(
        "mma.sync.aligned.m16n8k16.row.col.f32.bf16.bf16.f32 "
        "{%0,%1,%2,%3}, {%4,%5,%6,%7}, {%8,%9}, {%0,%1,%2,%3};"
        : "+f"(c[0]), "+f"(c[1]), "+f"(c[2]), "+f"(c[3])
        : "r"(a[0]), "r"(a[1]), "r"(a[2]), "r"(a[3]), "r"(b0), "r"(b1));
}

// ============================================================================
// Kernel 0: fp32 -> bf16 hi/lo split.  sel: 0=X, 1..3 = Wq/Wk/Wv.
// ============================================================================
__global__ __launch_bounds__(256, 1)
void split_bf16_kernel(const float* __restrict__ src, int sel, int n4) {
    int i = blockIdx.x * blockDim.x + threadIdx.x;
    if (i >= n4) return;
    __nv_bfloat16 *hi, *lo;
    if (sel == 0) { hi = g_Xhi; lo = g_Xlo; }
    else { hi = g_Whi + (size_t)(sel - 1) * E_DIM * E_DIM;
           lo = g_Wlo + (size_t)(sel - 1) * E_DIM * E_DIM; }
    float4 v = ((const float4*)src)[i];
    __nv_bfloat16 h0 = __float2bfloat16_rn(v.x), h1 = __float2bfloat16_rn(v.y);
    __nv_bfloat16 h2 = __float2bfloat16_rn(v.z), h3 = __float2bfloat16_rn(v.w);
    __nv_bfloat16 l0 = __float2bfloat16_rn(v.x - __bfloat162float(h0));
    __nv_bfloat16 l1 = __float2bfloat16_rn(v.y - __bfloat162float(h1));
    __nv_bfloat16 l2 = __float2bfloat16_rn(v.z - __bfloat162float(h2));
    __nv_bfloat16 l3 = __float2bfloat16_rn(v.w - __bfloat162float(h3));
    ((__nv_bfloat162*)hi)[2 * i]     = __halves2bfloat162(h0, h1);
    ((__nv_bfloat162*)hi)[2 * i + 1] = __halves2bfloat162(h2, h3);
    ((__nv_bfloat162*)lo)[2 * i]     = __halves2bfloat162(l0, l1);
    ((__nv_bfloat162*)lo)[2 * i + 1] = __halves2bfloat162(l2, l3);
}

// ============================================================================
// Kernel 1: bf16x3 GEMM via mma.sync (HMMA).  Out[m,n]=sum_k X[m,k]W[n,k]+b[n]
// BM=BN=128, K-chunk=64, cp.async double buffer, 8 warps of 64x32 tiles.
// grid = (8, 32, 3)  z selects Q/K/V.
// ============================================================================
#define KC 64
#define NCHUNK (E_DIM / KC)            // 16
#define RS 144                          // smem row stride bytes (64 bf16 + pad)
#define T_AHI 0
#define T_ALO 18432
#define T_BHI 36864
#define T_BLO 55296
#define STAGE 73728
#define GEMM_SMEM (2 * STAGE)           // 147456

__device__ __forceinline__ void issue_chunk(uint32_t sdst, int kc, int m0, int n0,
                                            const __nv_bfloat16* Whi,
                                            const __nv_bfloat16* Wlo, int tid) {
#pragma unroll
    for (int t4 = 0; t4 < 4; t4++) {
        const int idx = tid + t4 * 256;         // 0..1023
        const int r = idx >> 3, c = idx & 7;    // row, 16B unit
        const uint32_t so = (uint32_t)(r * RS + c * 16);
        const size_t goA = (size_t)(m0 + r) * E_DIM + kc * KC + c * 8;
        const size_t goB = (size_t)(n0 + r) * E_DIM + kc * KC + c * 8;
        cp_async16(sdst + T_AHI + so, g_Xhi + goA);
        cp_async16(sdst + T_ALO + so, g_Xlo + goA);
        cp_async16(sdst + T_BHI + so, Whi + goB);
        cp_async16(sdst + T_BLO + so, Wlo + goB);
    }
}

__global__ __launch_bounds__(256, 1)
void hmma_gemm_kernel(const float* __restrict__ bq, const float* __restrict__ bk,
                      const float* __restrict__ bv) {
    extern __shared__ char dsm[];
    const uint32_t sbase = smem_u32(dsm);
    const int tid  = threadIdx.x;
    const int wid  = tid >> 5;
    const int lane = tid & 31;
    const int n0 = blockIdx.x * 128;
    const int m0 = blockIdx.y * 128;
    const int z  = blockIdx.z;

    const __nv_bfloat16* Whi = g_Whi + (size_t)z * E_DIM * E_DIM;
    const __nv_bfloat16* Wlo = g_Wlo + (size_t)z * E_DIM * E_DIM;
    const float* bias = (z == 0) ? bq : (z == 1) ? bk : bv;
    float* Out = (z == 0) ? g_Q : (z == 1) ? g_K : g_V;

    const int wm = wid & 1;        // 0/1 -> 64-row half
    const int wn = wid >> 1;       // 0..3 -> 32-col quarter

    float acc[4][4][4];
#pragma unroll
    for (int mt = 0; mt < 4; mt++)
#pragma unroll
        for (int nt = 0; nt < 4; nt++)
#pragma unroll
            for (int j = 0; j < 4; j++) acc[mt][nt][j] = 0.f;

    // ldmatrix lane offset: (lane%16)*RS + (lane/16)*16
    const uint32_t laneOff = (uint32_t)((lane & 15) * RS + (lane >> 4) * 16);

    issue_chunk(sbase, 0, m0, n0, Whi, Wlo, tid);
    CP_COMMIT();

    for (int c = 0; c < NCHUNK; c++) {
        const uint32_t sbuf = sbase + (uint32_t)(c & 1) * STAGE;
        if (c + 1 < NCHUNK) {
            issue_chunk(sbase + (uint32_t)((c + 1) & 1) * STAGE, c + 1, m0, n0,
                        Whi, Wlo, tid);
            CP_COMMIT();
            CP_WAIT(1);
        } else {
            CP_WAIT(0);
        }
        __syncthreads();

        // 3 combos: (Ahi,Bhi), (Ahi,Blo), (Alo,Bhi)
#pragma unroll
        for (int combo = 0; combo < 3; combo++) {
            const uint32_t sA = sbuf + ((combo == 2) ? T_ALO : T_AHI) +
                                (uint32_t)(wm * 64) * RS + laneOff;
            const uint32_t sB = sbuf + ((combo == 1) ? T_BLO : T_BHI) +
                                (uint32_t)(wn * 32) * RS + laneOff;
#pragma unroll
            for (int ks = 0; ks < 4; ks++) {
                uint32_t a[4][4];
#pragma unroll
                for (int mt = 0; mt < 4; mt++)
                    ldmx4(a[mt], sA + (uint32_t)(mt * 16) * RS + ks * 32);
                uint32_t b[2][4];
#pragma unroll
                for (int p = 0; p < 2; p++)
                    ldmx4(b[p], sB + (uint32_t)(p * 16) * RS + ks * 32);
#pragma unroll
                for (int mt = 0; mt < 4; mt++) {
#pragma unroll
                    for (int nt = 0; nt < 4; nt++) {
                        const int p = nt >> 1, s = nt & 1;
                        mma16816(acc[mt][nt], a[mt], b[p][s], b[p][s + 2]);
                    }
                }
            }
        }
        __syncthreads();
    }

    // epilogue: direct stores (4-lane float2 groups fill 32B sectors)
    const int g   = lane >> 2;
    const int tig = lane & 3;
#pragma unroll
    for (int mt = 0; mt < 4; mt++) {
        const int rbase = m0 + wm * 64 + mt * 16 + g;
#pragma unroll
        for (int nt = 0; nt < 4; nt++) {
            const int ncol = n0 + wn * 32 + nt * 8 + tig * 2;
            const float b0 = bias[ncol], b1 = bias[ncol + 1];
            float2 v0 = make_float2(acc[mt][nt][0] + b0, acc[mt][nt][1] + b1);
            float2 v1 = make_float2(acc[mt][nt][2] + b0, acc[mt][nt][3] + b1);
            *(float2*)&Out[(size_t)rbase * E_DIM + ncol]       = v0;
            *(float2*)&Out[(size_t)(rbase + 8) * E_DIM + ncol] = v1;
        }
    }
}

// ============================================================================
// Kernel 2: V_total[b,h,d] = sum over all 2048 keys of v[b,h,j,d]
// ============================================================================
__global__ __launch_bounds__(512, 1)
void vtotal_kernel() {
    const int bh = blockIdx.x;
    const float* Vb = g_V + (size_t)bh * 128 * E_DIM;
    const int tid = threadIdx.x;
    const int d = tid & 63;
    const int g = tid >> 6;
    float s = 0.f;
    for (int r = g; r < 128; r += 8) {
        const float* row = Vb + (size_t)r * E_DIM;
#pragma unroll
        for (int cb = 0; cb < 16; cb++) s += row[cb * 64 + d];
    }
    __shared__ float red[8][64];
    red[g][d] = s;
    __syncthreads();
    if (tid < 64) {
        float tt = 0.f;
#pragma unroll
        for (int i2 = 0; i2 < 8; i2++) tt += red[i2][tid];
        g_Vtot[bh * 64 + tid] = tt;
    }
}

// ============================================================================
// Kernel 3: windowed attention with zero-padded softmax (unchanged).
// ============================================================================
#define KS_STRIDE 321
#define VS_STRIDE 68
#define OFF_Q     0
#define OFF_KS    1024
#define OFF_VS    (OFF_KS + 64 * KS_STRIDE)
#define OFF_SS    (OFF_VS + 272 * VS_STRIDE)
#define OFF_PART  (OFF_SS + 16 * 272)
#define OFF_PART2 (OFF_PART + 16 * 64)
#define OFF_DEN   (OFF_PART2 + 256)
#define OFF_VT    (OFF_DEN + 16)
#define ATTN_SMEM_FLOATS (OFF_VT + 64)
#define ATTN_SMEM_BYTES  (ATTN_SMEM_FLOATS * 4)

__global__ __launch_bounds__(256, 1)
void attn_kernel(float* __restrict__ out) {
    extern __shared__ float sm[];
    float* q_s   = sm + OFF_Q;
    float* ks    = sm + OFF_KS;
    float* vs    = sm + OFF_VS;
    float* s_s   = sm + OFF_SS;
    float* part  = sm + OFF_PART;
    float* part2 = sm + OFF_PART2;
    float* den   = sm + OFF_DEN;
    float* vt    = sm + OFF_VT;

    const int t   = blockIdx.x;
    const int h   = blockIdx.y;
    const int b   = blockIdx.z;
    const int tid = threadIdx.x;

    const size_t headbase = ((size_t)b * S_LEN + (size_t)h * 128) * E_DIM;
    const float* Qrow = g_Q + headbase + (size_t)t * E_DIM;
    const float* Kh   = g_K + headbase;
    const float* Vh   = g_V + headbase;

    *(float4*)&q_s[tid * 4] = *(const float4*)&Qrow[tid * 4];
    if (tid < 64) vt[tid] = g_Vtot[((b * NH) + h) * HD + tid];

    const int r0 = t - 8;
    for (int e4 = tid; e4 < 17 * 256; e4 += 256) {
        const int rro = e4 >> 8;
        const int c4  = (e4 & 255) << 2;
        const int rr  = r0 + rro;
        if (rr >= 0 && rr < 128) {
            float4 kv4 = *(const float4*)(Kh + (size_t)rr * E_DIM + c4);
            float4 vv4 = *(const float4*)(Vh + (size_t)rr * E_DIM + c4);
            const int d0 = c4 & 63;
            const int jl = (rro << 4) + (c4 >> 6);
            ks[(d0 + 0) * KS_STRIDE + jl] = kv4.x;
            ks[(d0 + 1) * KS_STRIDE + jl] = kv4.y;
            ks[(d0 + 2) * KS_STRIDE + jl] = kv4.z;
            ks[(d0 + 3) * KS_STRIDE + jl] = kv4.w;
            *(float4*)&vs[jl * VS_STRIDE + d0] = vv4;
        }
    }
    __syncthreads();

    const int qb = tid >> 6;
    const int kt = tid & 63;
    float accs[4][5];
#pragma unroll
    for (int qq = 0; qq < 4; qq++)
#pragma unroll
        for (int c = 0; c < 5; c++) accs[qq][c] = 0.f;

#pragma unroll 8
    for (int d = 0; d < 64; d++) {
        float kvv[5];
#pragma unroll
        for (int c = 0; c < 5; c++) kvv[c] = ks[d * KS_STRIDE + kt + 64 * c];
#pragma unroll
        for (int qq = 0; qq < 4; qq++) {
            const float qv = q_s[(qb * 4 + qq) * 64 + d];
#pragma unroll
            for (int c = 0; c < 5; c++) accs[qq][c] = fmaf(qv, kvv[c], accs[qq][c]);
        }
    }

    const float scale = 0.125f;
#pragma unroll
    for (int qq = 0; qq < 4; qq++) {
        const int qi = qb * 4 + qq;
        const int i  = t * 16 + qi;
        float rp = 0.f;
#pragma unroll
        for (int c = 0; c < 5; c++) {
            const int jl = kt + 64 * c;
            if (jl < 272) {
                const int j = r0 * 16 + jl;
                const bool win = (j >= 0) && (j < S_LEN) && (j >= i - WWIN) && (j < i + WWIN);
                float w = 0.f;
                if (win) w = __expf(accs[qq][c] * scale) - 1.f;
                s_s[qi * 272 + jl] = w;
                rp += w;
            }
        }
        part[qi * 64 + kt] = rp;
    }
    __syncthreads();

    {
        const int qi = tid >> 4, sg = tid & 15;
        part2[qi * 16 + sg] = part[qi * 64 + sg] + part[qi * 64 + sg + 16] +
                              part[qi * 64 + sg + 32] + part[qi * 64 + sg + 48];
    }
    __syncthreads();
    if (tid < 16) {
        float ssum = 0.f;
#pragma unroll
        for (int sg = 0; sg < 16; sg++) ssum += part2[tid * 16 + sg];
        den[tid] = (float)S_LEN + ssum;
    }

    const int p   = tid >> 6;
    const int qb2 = (tid >> 4) & 3;
    const int dl  = tid & 15;
    float4 oacc[4];
#pragma unroll
    for (int qq = 0; qq < 4; qq++) oacc[qq] = make_float4(0.f, 0.f, 0.f, 0.f);

    for (int jl = p; jl < 272; jl += 4) {
        const float4 v4 = *(const float4*)&vs[jl * VS_STRIDE + dl * 4];
#pragma unroll
        for (int qq = 0; qq < 4; qq++) {
            const float w = s_s[(qb2 * 4 + qq) * 272 + jl];
            oacc[qq].x = fmaf(w, v4.x, oacc[qq].x);
            oacc[qq].y = fmaf(w, v4.y, oacc[qq].y);
            oacc[qq].z = fmaf(w, v4.z, oacc[qq].z);
            oacc[qq].w = fmaf(w, v4.w, oacc[qq].w);
        }
    }
    float* opart = ks;
#pragma unroll
    for (int qq = 0; qq < 4; qq++)
        *(float4*)&opart[(p * 16 + qb2 * 4 + qq) * 64 + dl * 4] = oacc[qq];
    __syncthreads();

    {
        const int qi = tid >> 4;
        const int dc = tid & 15;
        float4 sum = *(const float4*)&vt[dc * 4];
#pragma unroll
        for (int pp = 0; pp < 4; pp++) {
            const float4 o = *(const float4*)&opart[(pp * 16 + qi) * 64 + dc * 4];
            sum.x += o.x; sum.y += o.y; sum.z += o.z; sum.w += o.w;
        }
        const float inv = 1.0f / den[qi];
        sum.x *= inv; sum.y *= inv; sum.z *= inv; sum.w *= inv;
        const int i = t * 16 + qi;
        *(float4*)&out[((size_t)b * S_LEN + i) * E_DIM + h * HD + dc * 4] = sum;
    }
}

// ============================================================================
// kernel_launch
// ============================================================================
extern "C" void kernel_launch(void* const* d_in, const int* in_sizes, int n_in,
                              void* d_out, int out_size) {
    (void)in_sizes; (void)n_in; (void)out_size;
    const float* x  = (const float*)d_in[0];
    const float* Wq = (const float*)d_in[1];
    const float* bq = (const float*)d_in[2];
    const float* Wk = (const float*)d_in[3];
    const float* bk = (const float*)d_in[4];
    const float* Wv = (const float*)d_in[5];
    const float* bv = (const float*)d_in[6];
    float* out = (float*)d_out;

    // bf16 hi/lo split pre-pass
    split_bf16_kernel<<<(M_TOT * E_DIM / 4 + 255) / 256, 256>>>(x, 0, M_TOT * E_DIM / 4);
    split_bf16_kernel<<<(E_DIM * E_DIM / 4 + 255) / 256, 256>>>(Wq, 1, E_DIM * E_DIM / 4);
    split_bf16_kernel<<<(E_DIM * E_DIM / 4 + 255) / 256, 256>>>(Wk, 2, E_DIM * E_DIM / 4);
    split_bf16_kernel<<<(E_DIM * E_DIM / 4 + 255) / 256, 256>>>(Wv, 3, E_DIM * E_DIM / 4);

    // HMMA QKV GEMM
    cudaFuncSetAttribute(hmma_gemm_kernel, cudaFuncAttributeMaxDynamicSharedMemorySize,
                         GEMM_SMEM);
    dim3 gg(E_DIM / 128, M_TOT / 128, 3);   // (8, 32, 3)
    hmma_gemm_kernel<<<gg, 256, GEMM_SMEM>>>(bq, bk, bv);

    vtotal_kernel<<<BATCH * NH, 512>>>();

    cudaFuncSetAttribute(attn_kernel, cudaFuncAttributeMaxDynamicSharedMemorySize,
                         ATTN_SMEM_BYTES);
    dim3 g3(128, NH, BATCH);
    attn_kernel<<<g3, 256, ATTN_SMEM_BYTES>>>(out);
}

// round 6
// speedup vs baseline: 1.5749x; 1.1818x over previous
#include <cuda_runtime.h>
#include <cuda_bf16.h>
#include <cuda_fp16.h>
#include <cstdint>

#define S_LEN 2048
#define E_DIM 1024
#define NH    16
#define HD    64
#define WWIN  128
#define BATCH 2
#define M_TOT (BATCH * S_LEN)   // 4096

// ---------------- scratch (device globals; no allocations allowed) ----------------
__device__ float g_Q[M_TOT * E_DIM];
__device__ float g_K[M_TOT * E_DIM];
__device__ float g_V[M_TOT * E_DIM];
__device__ float g_Vtot[BATCH * NH * HD];
__device__ __nv_bfloat16 g_Xhi[M_TOT * E_DIM];
__device__ __nv_bfloat16 g_Xlo[M_TOT * E_DIM];
__device__ __nv_bfloat16 g_Whi[3 * E_DIM * E_DIM];
__device__ __nv_bfloat16 g_Wlo[3 * E_DIM * E_DIM];

// ---------------- PTX helpers (baseline ISA only) ----------------
__device__ __forceinline__ uint32_t smem_u32(const void* p) {
    uint32_t a;
    asm("{ .reg .u64 t; cvta.to.shared.u64 t, %1; cvt.u32.u64 %0, t; }" : "=r"(a) : "l"(p));
    return a;
}
__device__ __forceinline__ void cp_async16(uint32_t s, const void* g) {
    asm volatile("cp.async.cg.shared.global [%0], [%1], 16;" :: "r"(s), "l"(g) : "memory");
}
#define CP_COMMIT() asm volatile("cp.async.commit_group;" ::: "memory")
#define CP_WAIT(n)  asm volatile("cp.async.wait_group %0;" :: "n"(n) : "memory")

__device__ __forceinline__ void ldmx4(uint32_t r[4], uint32_t addr) {
    asm volatile("ldmatrix.sync.aligned.m8n8.x4.shared.b16 {%0,%1,%2,%3}, [%4];"
                 : "=r"(r[0]), "=r"(r[1]), "=r"(r[2]), "=r"(r[3]) : "r"(addr));
}
__device__ __forceinline__ void mma16816(float c[4], const uint32_t a[4],
                                         uint32_t b0, uint32_t b1) {
    asm volatile(
        "mma.sync.aligned.m16n8k16.row.col.f32.bf16.bf16.f32 "
        "{%0,%1,%2,%3}, {%4,%5,%6,%7}, {%8,%9}, {%0,%1,%2,%3};"
        : "+f"(c[0]), "+f"(c[1]), "+f"(c[2]), "+f"(c[3])
        : "r"(a[0]), "r"(a[1]), "r"(a[2]), "r"(a[3]), "r"(b0), "r"(b1));
}
__device__ __forceinline__ void mma16816h(float c[4], const uint32_t a[4],
                                          uint32_t b0, uint32_t b1) {
    asm volatile(
        "mma.sync.aligned.m16n8k16.row.col.f32.f16.f16.f32 "
        "{%0,%1,%2,%3}, {%4,%5,%6,%7}, {%8,%9}, {%0,%1,%2,%3};"
        : "+f"(c[0]), "+f"(c[1]), "+f"(c[2]), "+f"(c[3])
        : "r"(a[0]), "r"(a[1]), "r"(a[2]), "r"(a[3]), "r"(b0), "r"(b1));
}

// ============================================================================
// Kernel 0: fp32 -> bf16 hi/lo split.  sel: 0=X, 1..3 = Wq/Wk/Wv.
// ============================================================================
__global__ __launch_bounds__(256, 1)
void split_bf16_kernel(const float* __restrict__ src, int sel, int n4) {
    int i = blockIdx.x * blockDim.x + threadIdx.x;
    if (i >= n4) return;
    __nv_bfloat16 *hi, *lo;
    if (sel == 0) { hi = g_Xhi; lo = g_Xlo; }
    else { hi = g_Whi + (size_t)(sel - 1) * E_DIM * E_DIM;
           lo = g_Wlo + (size_t)(sel - 1) * E_DIM * E_DIM; }
    float4 v = ((const float4*)src)[i];
    __nv_bfloat16 h0 = __float2bfloat16_rn(v.x), h1 = __float2bfloat16_rn(v.y);
    __nv_bfloat16 h2 = __float2bfloat16_rn(v.z), h3 = __float2bfloat16_rn(v.w);
    __nv_bfloat16 l0 = __float2bfloat16_rn(v.x - __bfloat162float(h0));
    __nv_bfloat16 l1 = __float2bfloat16_rn(v.y - __bfloat162float(h1));
    __nv_bfloat16 l2 = __float2bfloat16_rn(v.z - __bfloat162float(h2));
    __nv_bfloat16 l3 = __float2bfloat16_rn(v.w - __bfloat162float(h3));
    ((__nv_bfloat162*)hi)[2 * i]     = __halves2bfloat162(h0, h1);
    ((__nv_bfloat162*)hi)[2 * i + 1] = __halves2bfloat162(h2, h3);
    ((__nv_bfloat162*)lo)[2 * i]     = __halves2bfloat162(l0, l1);
    ((__nv_bfloat162*)lo)[2 * i + 1] = __halves2bfloat162(l2, l3);
}

// ============================================================================
// Kernel 1: bf16x3 GEMM via mma.sync (HMMA) — verified in R4, unchanged.
// ============================================================================
#define KC 64
#define NCHUNK (E_DIM / KC)
#define RS 144
#define T_AHI 0
#define T_ALO 18432
#define T_BHI 36864
#define T_BLO 55296
#define STAGE 73728
#define GEMM_SMEM (2 * STAGE)

__device__ __forceinline__ void issue_chunk(uint32_t sdst, int kc, int m0, int n0,
                                            const __nv_bfloat16* Whi,
                                            const __nv_bfloat16* Wlo, int tid) {
#pragma unroll
    for (int t4 = 0; t4 < 4; t4++) {
        const int idx = tid + t4 * 256;
        const int r = idx >> 3, c = idx & 7;
        const uint32_t so = (uint32_t)(r * RS + c * 16);
        const size_t goA = (size_t)(m0 + r) * E_DIM + kc * KC + c * 8;
        const size_t goB = (size_t)(n0 + r) * E_DIM + kc * KC + c * 8;
        cp_async16(sdst + T_AHI + so, g_Xhi + goA);
        cp_async16(sdst + T_ALO + so, g_Xlo + goA);
        cp_async16(sdst + T_BHI + so, Whi + goB);
        cp_async16(sdst + T_BLO + so, Wlo + goB);
    }
}

__global__ __launch_bounds__(256, 1)
void hmma_gemm_kernel(const float* __restrict__ bq, const float* __restrict__ bk,
                      const float* __restrict__ bv) {
    extern __shared__ char dsm[];
    const uint32_t sbase = smem_u32(dsm);
    const int tid  = threadIdx.x;
    const int wid  = tid >> 5;
    const int lane = tid & 31;
    const int n0 = blockIdx.x * 128;
    const int m0 = blockIdx.y * 128;
    const int z  = blockIdx.z;

    const __nv_bfloat16* Whi = g_Whi + (size_t)z * E_DIM * E_DIM;
    const __nv_bfloat16* Wlo = g_Wlo + (size_t)z * E_DIM * E_DIM;
    const float* bias = (z == 0) ? bq : (z == 1) ? bk : bv;
    float* Out = (z == 0) ? g_Q : (z == 1) ? g_K : g_V;

    const int wm = wid & 1;
    const int wn = wid >> 1;

    float acc[4][4][4];
#pragma unroll
    for (int mt = 0; mt < 4; mt++)
#pragma unroll
        for (int nt = 0; nt < 4; nt++)
#pragma unroll
            for (int j = 0; j < 4; j++) acc[mt][nt][j] = 0.f;

    const uint32_t laneOff = (uint32_t)((lane & 15) * RS + (lane >> 4) * 16);

    issue_chunk(sbase, 0, m0, n0, Whi, Wlo, tid);
    CP_COMMIT();

    for (int c = 0; c < NCHUNK; c++) {
        const uint32_t sbuf = sbase + (uint32_t)(c & 1) * STAGE;
        if (c + 1 < NCHUNK) {
            issue_chunk(sbase + (uint32_t)((c + 1) & 1) * STAGE, c + 1, m0, n0,
                        Whi, Wlo, tid);
            CP_COMMIT();
            CP_WAIT(1);
        } else {
            CP_WAIT(0);
        }
        __syncthreads();

#pragma unroll
        for (int combo = 0; combo < 3; combo++) {
            const uint32_t sA = sbuf + ((combo == 2) ? T_ALO : T_AHI) +
                                (uint32_t)(wm * 64) * RS + laneOff;
            const uint32_t sB = sbuf + ((combo == 1) ? T_BLO : T_BHI) +
                                (uint32_t)(wn * 32) * RS + laneOff;
#pragma unroll
            for (int ks = 0; ks < 4; ks++) {
                uint32_t a[4][4];
#pragma unroll
                for (int mt = 0; mt < 4; mt++)
                    ldmx4(a[mt], sA + (uint32_t)(mt * 16) * RS + ks * 32);
                uint32_t b[2][4];
#pragma unroll
                for (int p = 0; p < 2; p++)
                    ldmx4(b[p], sB + (uint32_t)(p * 16) * RS + ks * 32);
#pragma unroll
                for (int mt = 0; mt < 4; mt++) {
#pragma unroll
                    for (int nt = 0; nt < 4; nt++) {
                        const int p = nt >> 1, s = nt & 1;
                        mma16816(acc[mt][nt], a[mt], b[p][s], b[p][s + 2]);
                    }
                }
            }
        }
        __syncthreads();
    }

    const int g   = lane >> 2;
    const int tig = lane & 3;
#pragma unroll
    for (int mt = 0; mt < 4; mt++) {
        const int rbase = m0 + wm * 64 + mt * 16 + g;
#pragma unroll
        for (int nt = 0; nt < 4; nt++) {
            const int ncol = n0 + wn * 32 + nt * 8 + tig * 2;
            const float b0 = bias[ncol], b1 = bias[ncol + 1];
            float2 v0 = make_float2(acc[mt][nt][0] + b0, acc[mt][nt][1] + b1);
            float2 v1 = make_float2(acc[mt][nt][2] + b0, acc[mt][nt][3] + b1);
            *(float2*)&Out[(size_t)rbase * E_DIM + ncol]       = v0;
            *(float2*)&Out[(size_t)(rbase + 8) * E_DIM + ncol] = v1;
        }
    }
}

// ============================================================================
// Kernel 2: V_total[b,h,d]
// ============================================================================
__global__ __launch_bounds__(512, 1)
void vtotal_kernel() {
    const int bh = blockIdx.x;
    const float* Vb = g_V + (size_t)bh * 128 * E_DIM;
    const int tid = threadIdx.x;
    const int d = tid & 63;
    const int g = tid >> 6;
    float s = 0.f;
    for (int r = g; r < 128; r += 8) {
        const float* row = Vb + (size_t)r * E_DIM;
#pragma unroll
        for (int cb = 0; cb < 16; cb++) s += row[cb * 64 + d];
    }
    __shared__ float red[8][64];
    red[g][d] = s;
    __syncthreads();
    if (tid < 64) {
        float tt = 0.f;
#pragma unroll
        for (int i2 = 0; i2 < 8; i2++) tt += red[i2][tid];
        g_Vtot[bh * 64 + tid] = tt;
    }
}

// ============================================================================
// Kernel 3: tensor-core windowed attention, zero-padded softmax.
// CTA = (t, h, b): 16 queries x 272 keys.  f16 HMMA:
//   QK = Qhi*Khi + Qhi*Klo + Qlo*Khi  (error ~2^-22)
//   P = exp(score)-1 masked, packed f16 from C-frags (2 n8-tiles -> 1 k16 A-frag)
//   PV over Vt[d][j] f16 B-frags.  out = (Vtot + P@V)/(2048 + rowsum(P)).
// 256 threads, ~117KB smem.
// ============================================================================
#define A_OFF_VT   0
#define A_OFF_DEN  256
#define A_OFF_RS   320
#define A_OFF_QHI  1024
#define A_OFF_QLO  3328
#define A_OFF_KHI  5632
#define A_OFF_KLO  44800
#define A_OFF_VTR  83968
#define A_SMEM     119808
#define A_OFF_OP   A_OFF_KHI      // 8x16x64 f32 = 32KB, aliases Ks_hi post-sync
#define QS_B 144                  // 72 halves per row
#define VT_B 560                  // 280 halves per row

__device__ __forceinline__ uint32_t packh2(float a, float b) {
    __half2 h = __floats2half2_rn(a, b);
    return *(uint32_t*)&h;
}

__global__ __launch_bounds__(256, 1)
void attn_tc_kernel(float* __restrict__ out) {
    extern __shared__ char dsm[];
    const uint32_t sbase = smem_u32(dsm);
    const int t   = blockIdx.x;
    const int h   = blockIdx.y;
    const int b   = blockIdx.z;
    const int tid = threadIdx.x;
    const int wid = tid >> 5;
    const int lane = tid & 31;

    const size_t headbase = ((size_t)b * S_LEN + (size_t)h * 128) * E_DIM;
    const float* Qrow = g_Q + headbase + (size_t)t * E_DIM;
    const float* Kh   = g_K + headbase;
    const float* Vh   = g_V + headbase;

    __half* Qhi = (__half*)(dsm + A_OFF_QHI);
    __half* Qlo = (__half*)(dsm + A_OFF_QLO);
    __half* Khi = (__half*)(dsm + A_OFF_KHI);
    __half* Klo = (__half*)(dsm + A_OFF_KLO);
    __half* Vt  = (__half*)(dsm + A_OFF_VTR);
    float*  vt  = (float*)(dsm + A_OFF_VT);
    float*  den = (float*)(dsm + A_OFF_DEN);
    float*  rsp = (float*)(dsm + A_OFF_RS);

    // ---- load Q (1 row of 1024 floats -> 16 q x 64 d), f16 hi/lo ----
    {
        float4 qv = *(const float4*)&Qrow[tid * 4];
        const int qi = tid >> 4, dq = (tid & 15) * 4;
        float f[4] = {qv.x, qv.y, qv.z, qv.w};
        __half hh[4], hl[4];
#pragma unroll
        for (int m = 0; m < 4; m++) {
            hh[m] = __float2half_rn(f[m]);
            hl[m] = __float2half_rn(f[m] - __half2float(hh[m]));
        }
        __half* qh = &Qhi[qi * 72 + dq];
        __half* ql = &Qlo[qi * 72 + dq];
        ((__half2*)qh)[0] = __halves2half2(hh[0], hh[1]);
        ((__half2*)qh)[1] = __halves2half2(hh[2], hh[3]);
        ((__half2*)ql)[0] = __halves2half2(hl[0], hl[1]);
        ((__half2*)ql)[1] = __halves2half2(hl[2], hl[3]);
    }
    if (tid < 64) vt[tid] = g_Vtot[((b * NH) + h) * HD + tid];

    // ---- load K (hi/lo) rows + V transposed, zero-fill clipped rows ----
    const int r0 = t - 8;
    for (int e4 = tid; e4 < 17 * 256; e4 += 256) {
        const int rro = e4 >> 8;
        const int c4  = (e4 & 255) << 2;
        const int rr  = r0 + rro;
        const int jl  = (rro << 4) + (c4 >> 6);
        const int d0  = c4 & 63;
        float4 kv = make_float4(0.f, 0.f, 0.f, 0.f);
        float4 vv = make_float4(0.f, 0.f, 0.f, 0.f);
        if (rr >= 0 && rr < 128) {
            kv = *(const float4*)(Kh + (size_t)rr * E_DIM + c4);
            vv = *(const float4*)(Vh + (size_t)rr * E_DIM + c4);
        }
        float kf[4] = {kv.x, kv.y, kv.z, kv.w};
        float vf[4] = {vv.x, vv.y, vv.z, vv.w};
        __half khh[4], khl[4];
#pragma unroll
        for (int m = 0; m < 4; m++) {
            khh[m] = __float2half_rn(kf[m]);
            khl[m] = __float2half_rn(kf[m] - __half2float(khh[m]));
        }
        __half* kh = &Khi[jl * 72 + d0];
        __half* kl = &Klo[jl * 72 + d0];
        ((__half2*)kh)[0] = __halves2half2(khh[0], khh[1]);
        ((__half2*)kh)[1] = __halves2half2(khh[2], khh[3]);
        ((__half2*)kl)[0] = __halves2half2(khl[0], khl[1]);
        ((__half2*)kl)[1] = __halves2half2(khl[2], khl[3]);
#pragma unroll
        for (int m = 0; m < 4; m++)
            Vt[(d0 + m) * 280 + jl] = __float2half_rn(vf[m]);
    }
    __syncthreads();

    // ---- per-warp: QK mma -> exp/mask -> P frags -> PV mma ----
    const int g   = lane >> 2;
    const int tig = lane & 3;
    const uint32_t loQ = sbase + (uint32_t)((lane & 15) * QS_B + (lane >> 4) * 16);
    const uint32_t loV = sbase + (uint32_t)((lane & 15) * VT_B + (lane >> 4) * 16);
    const int i0 = t * 16 + g, i1 = i0 + 8;
    const int jgbase = r0 * 16;

    float oacc[8][4];
#pragma unroll
    for (int dt = 0; dt < 8; dt++)
#pragma unroll
        for (int j = 0; j < 4; j++) oacc[dt][j] = 0.f;
    float rs0 = 0.f, rs1 = 0.f;

    const int np = (wid == 7) ? 3 : 2;
    for (int pi = 0; pi < np; pi++) {
        const int pr = (pi == 0) ? wid : (pi == 1) ? (wid + 8) : 16;
        float c0[4] = {0.f, 0.f, 0.f, 0.f};
        float c1[4] = {0.f, 0.f, 0.f, 0.f};
#pragma unroll
        for (int ks = 0; ks < 4; ks++) {
            uint32_t ah[4], al[4], kh[4], kl[4];
            ldmx4(ah, loQ + A_OFF_QHI + ks * 32);
            ldmx4(al, loQ + A_OFF_QLO + ks * 32);
            ldmx4(kh, loQ + A_OFF_KHI + (uint32_t)pr * 2304 + ks * 32);
            ldmx4(kl, loQ + A_OFF_KLO + (uint32_t)pr * 2304 + ks * 32);
            mma16816h(c0, ah, kh[0], kh[2]);
            mma16816h(c0, ah, kl[0], kl[2]);
            mma16816h(c0, al, kh[0], kh[2]);
            mma16816h(c1, ah, kh[1], kh[3]);
            mma16816h(c1, ah, kl[1], kl[3]);
            mma16816h(c1, al, kh[1], kh[3]);
        }
        // mask + exp(s*scale)-1 + pack to f16 A-frags + row sums
        uint32_t pf[4];
#pragma unroll
        for (int s = 0; s < 2; s++) {
            const float* cc = s ? c1 : c0;
            const int jg0 = jgbase + pr * 16 + s * 8 + 2 * tig;
            const int jg1 = jg0 + 1;
            const bool ok0 = (jg0 >= 0) && (jg0 < S_LEN);
            const bool ok1 = (jg1 >= 0) && (jg1 < S_LEN);
            float w00 = (ok0 && jg0 >= i0 - WWIN && jg0 < i0 + WWIN)
                        ? (__expf(cc[0] * 0.125f) - 1.f) : 0.f;
            float w01 = (ok1 && jg1 >= i0 - WWIN && jg1 < i0 + WWIN)
                        ? (__expf(cc[1] * 0.125f) - 1.f) : 0.f;
            float w10 = (ok0 && jg0 >= i1 - WWIN && jg0 < i1 + WWIN)
                        ? (__expf(cc[2] * 0.125f) - 1.f) : 0.f;
            float w11 = (ok1 && jg1 >= i1 - WWIN && jg1 < i1 + WWIN)
                        ? (__expf(cc[3] * 0.125f) - 1.f) : 0.f;
            rs0 += w00 + w01;
            rs1 += w10 + w11;
            pf[s * 2 + 0] = packh2(w00, w01);
            pf[s * 2 + 1] = packh2(w10, w11);
        }
        // PV: A = pf (16q x 16j), B = Vt frags (8 d-tiles)
#pragma unroll
        for (int dp = 0; dp < 4; dp++) {
            uint32_t vb[4];
            ldmx4(vb, loV + A_OFF_VTR + (uint32_t)dp * 8960 + (uint32_t)pr * 32);
            mma16816h(oacc[dp * 2 + 0], pf, vb[0], vb[2]);
            mma16816h(oacc[dp * 2 + 1], pf, vb[1], vb[3]);
        }
    }

    // row-sum reduce over tig lanes
    rs0 += __shfl_xor_sync(0xFFFFFFFF, rs0, 1);
    rs0 += __shfl_xor_sync(0xFFFFFFFF, rs0, 2);
    rs1 += __shfl_xor_sync(0xFFFFFFFF, rs1, 1);
    rs1 += __shfl_xor_sync(0xFFFFFFFF, rs1, 2);
    if (tig == 0) {
        rsp[wid * 16 + g]     = rs0;
        rsp[wid * 16 + g + 8] = rs1;
    }
    __syncthreads();   // all Ks reads done; opart may alias Ks_hi now

    // store per-warp partial out [16 x 64]
    {
        float* op = (float*)(dsm + A_OFF_OP) + wid * 1024;
#pragma unroll
        for (int dt = 0; dt < 8; dt++) {
            *(float2*)&op[g * 64 + dt * 8 + 2 * tig] =
                make_float2(oacc[dt][0], oacc[dt][1]);
            *(float2*)&op[(g + 8) * 64 + dt * 8 + 2 * tig] =
                make_float2(oacc[dt][2], oacc[dt][3]);
        }
    }
    if (tid < 16) {
        float s = 0.f;
#pragma unroll
        for (int w8 = 0; w8 < 8; w8++) s += rsp[w8 * 16 + tid];
        den[tid] = (float)S_LEN + s;
    }
    __syncthreads();

    // combine partials + Vtot, normalize, write out
    {
        const int qi = tid >> 4;
        const int dc = tid & 15;
        const float* opf = (const float*)(dsm + A_OFF_OP);
        float4 sum = *(const float4*)&vt[dc * 4];
#pragma unroll
        for (int w8 = 0; w8 < 8; w8++) {
            const float4 o = *(const float4*)&opf[w8 * 1024 + qi * 64 + dc * 4];
            sum.x += o.x; sum.y += o.y; sum.z += o.z; sum.w += o.w;
        }
        const float inv = 1.0f / den[qi];
        sum.x *= inv; sum.y *= inv; sum.z *= inv; sum.w *= inv;
        const int i = t * 16 + qi;
        *(float4*)&out[((size_t)b * S_LEN + i) * E_DIM + h * HD + dc * 4] = sum;
    }
}

// ============================================================================
// kernel_launch
// ============================================================================
extern "C" void kernel_launch(void* const* d_in, const int* in_sizes, int n_in,
                              void* d_out, int out_size) {
    (void)in_sizes; (void)n_in; (void)out_size;
    const float* x  = (const float*)d_in[0];
    const float* Wq = (const float*)d_in[1];
    const float* bq = (const float*)d_in[2];
    const float* Wk = (const float*)d_in[3];
    const float* bk = (const float*)d_in[4];
    const float* Wv = (const float*)d_in[5];
    const float* bv = (const float*)d_in[6];
    float* out = (float*)d_out;

    split_bf16_kernel<<<(M_TOT * E_DIM / 4 + 255) / 256, 256>>>(x, 0, M_TOT * E_DIM / 4);
    split_bf16_kernel<<<(E_DIM * E_DIM / 4 + 255) / 256, 256>>>(Wq, 1, E_DIM * E_DIM / 4);
    split_bf16_kernel<<<(E_DIM * E_DIM / 4 + 255) / 256, 256>>>(Wk, 2, E_DIM * E_DIM / 4);
    split_bf16_kernel<<<(E_DIM * E_DIM / 4 + 255) / 256, 256>>>(Wv, 3, E_DIM * E_DIM / 4);

    cudaFuncSetAttribute(hmma_gemm_kernel, cudaFuncAttributeMaxDynamicSharedMemorySize,
                         GEMM_SMEM);
    dim3 gg(E_DIM / 128, M_TOT / 128, 3);
    hmma_gemm_kernel<<<gg, 256, GEMM_SMEM>>>(bq, bk, bv);

    vtotal_kernel<<<BATCH * NH, 512>>>();

    cudaFuncSetAttribute(attn_tc_kernel, cudaFuncAttributeMaxDynamicSharedMemorySize,
                         A_SMEM);
    dim3 g3(128, NH, BATCH);
    attn_tc_kernel<<<g3, 256, A_SMEM>>>(out);
}

// round 8
// speedup vs baseline: 2.4366x; 1.5472x over previous
#include <cuda_runtime.h>
#include <cuda_fp16.h>
#include <cstdint>

#define S_LEN 2048
#define E_DIM 1024
#define NH    16
#define HD    64
#define WWIN  128
#define BATCH 2
#define M_TOT (BATCH * S_LEN)   // 4096

// ---------------- scratch (device globals; no allocations allowed) ----------------
__device__ float g_Vtot[BATCH * NH * HD];
__device__ __half g_Xh16[M_TOT * E_DIM];
__device__ __half g_Xl16[M_TOT * E_DIM];
__device__ __half g_Wh16[3 * E_DIM * E_DIM];
// GEMM outputs, pre-split for attention
__device__ __half g_Qh[M_TOT * E_DIM];
__device__ __half g_Ql[M_TOT * E_DIM];
__device__ __half g_Kh[M_TOT * E_DIM];
__device__ __half g_Kl[M_TOT * E_DIM];
__device__ __half g_Vh[M_TOT * E_DIM];

// ---------------- PTX helpers (baseline ISA only) ----------------
__device__ __forceinline__ uint32_t smem_u32(const void* p) {
    uint32_t a;
    asm("{ .reg .u64 t; cvta.to.shared.u64 t, %1; cvt.u32.u64 %0, t; }" : "=r"(a) : "l"(p));
    return a;
}
__device__ __forceinline__ void cp_async16(uint32_t s, const void* g) {
    asm volatile("cp.async.cg.shared.global [%0], [%1], 16;" :: "r"(s), "l"(g) : "memory");
}
#define CP_COMMIT() asm volatile("cp.async.commit_group;" ::: "memory")
#define CP_WAIT(n)  asm volatile("cp.async.wait_group %0;" :: "n"(n) : "memory")

__device__ __forceinline__ void ldmx4(uint32_t r[4], uint32_t addr) {
    asm volatile("ldmatrix.sync.aligned.m8n8.x4.shared.b16 {%0,%1,%2,%3}, [%4];"
                 : "=r"(r[0]), "=r"(r[1]), "=r"(r[2]), "=r"(r[3]) : "r"(addr));
}
__device__ __forceinline__ void ldmx4t(uint32_t r[4], uint32_t addr) {
    asm volatile("ldmatrix.sync.aligned.m8n8.x4.trans.shared.b16 {%0,%1,%2,%3}, [%4];"
                 : "=r"(r[0]), "=r"(r[1]), "=r"(r[2]), "=r"(r[3]) : "r"(addr));
}
__device__ __forceinline__ void mma16816h(float c[4], const uint32_t a[4],
                                          uint32_t b0, uint32_t b1) {
    asm volatile(
        "mma.sync.aligned.m16n8k16.row.col.f32.f16.f16.f32 "
        "{%0,%1,%2,%3}, {%4,%5,%6,%7}, {%8,%9}, {%0,%1,%2,%3};"
        : "+f"(c[0]), "+f"(c[1]), "+f"(c[2]), "+f"(c[3])
        : "r"(a[0]), "r"(a[1]), "r"(a[2]), "r"(a[3]), "r"(b0), "r"(b1));
}

// ============================================================================
// Kernel 0: fp32 -> f16 split.  sel 0: X -> hi/lo.  sel 1..3: W -> single f16.
// ============================================================================
__global__ __launch_bounds__(256, 1)
void split_f16_kernel(const float* __restrict__ src, int sel, int n4) {
    int i = blockIdx.x * blockDim.x + threadIdx.x;
    if (i >= n4) return;
    float4 v = ((const float4*)src)[i];
    if (sel == 0) {
        __half h0 = __float2half_rn(v.x), h1 = __float2half_rn(v.y);
        __half h2 = __float2half_rn(v.z), h3 = __float2half_rn(v.w);
        __half l0 = __float2half_rn(v.x - __half2float(h0));
        __half l1 = __float2half_rn(v.y - __half2float(h1));
        __half l2 = __float2half_rn(v.z - __half2float(h2));
        __half l3 = __float2half_rn(v.w - __half2float(h3));
        ((__half2*)g_Xh16)[2 * i]     = __halves2half2(h0, h1);
        ((__half2*)g_Xh16)[2 * i + 1] = __halves2half2(h2, h3);
        ((__half2*)g_Xl16)[2 * i]     = __halves2half2(l0, l1);
        ((__half2*)g_Xl16)[2 * i + 1] = __halves2half2(l2, l3);
    } else {
        __half* w = g_Wh16 + (size_t)(sel - 1) * E_DIM * E_DIM;
        ((__half2*)w)[2 * i]     = __floats2half2_rn(v.x, v.y);
        ((__half2*)w)[2 * i + 1] = __floats2half2_rn(v.z, v.w);
    }
}

// ============================================================================
// Kernel 1: f16 2-product GEMM via mma.sync.
//   Out = (Xhi + Xlo) @ W16.T + b   (error = W f16 quantization only)
// Epilogue writes f16 hi/lo (Q,K) or f16 (V) directly — no f32 output.
// BM=BN=128, KC=64, cp.async double buffer, 8 warps of 64x32.
// ============================================================================
#define KC 64
#define NCHUNK (E_DIM / KC)
#define RS 144
#define T_AHI 0
#define T_ALO 18432
#define T_BHI 36864
#define STAGE 55296
#define GEMM_SMEM (2 * STAGE)   // 110592

__device__ __forceinline__ void issue_chunk(uint32_t sdst, int kc, int m0, int n0,
                                            const __half* Wh, int tid) {
#pragma unroll
    for (int t4 = 0; t4 < 4; t4++) {
        const int idx = tid + t4 * 256;
        const int r = idx >> 3, c = idx & 7;
        const uint32_t so = (uint32_t)(r * RS + c * 16);
        const size_t goA = (size_t)(m0 + r) * E_DIM + kc * KC + c * 8;
        const size_t goB = (size_t)(n0 + r) * E_DIM + kc * KC + c * 8;
        cp_async16(sdst + T_AHI + so, g_Xh16 + goA);
        cp_async16(sdst + T_ALO + so, g_Xl16 + goA);
        cp_async16(sdst + T_BHI + so, Wh + goB);
    }
}

__global__ __launch_bounds__(256, 1)
void hmma_gemm_kernel(const float* __restrict__ bq, const float* __restrict__ bk,
                      const float* __restrict__ bv) {
    extern __shared__ char dsm[];
    const uint32_t sbase = smem_u32(dsm);
    const int tid  = threadIdx.x;
    const int wid  = tid >> 5;
    const int lane = tid & 31;
    const int n0 = blockIdx.x * 128;
    const int m0 = blockIdx.y * 128;
    const int z  = blockIdx.z;

    const __half* Wh = g_Wh16 + (size_t)z * E_DIM * E_DIM;
    const float* bias = (z == 0) ? bq : (z == 1) ? bk : bv;

    const int wm = wid & 1;
    const int wn = wid >> 1;

    float acc[4][4][4];
#pragma unroll
    for (int mt = 0; mt < 4; mt++)
#pragma unroll
        for (int nt = 0; nt < 4; nt++)
#pragma unroll
            for (int j = 0; j < 4; j++) acc[mt][nt][j] = 0.f;

    const uint32_t laneOff = (uint32_t)((lane & 15) * RS + (lane >> 4) * 16);

    issue_chunk(sbase, 0, m0, n0, Wh, tid);
    CP_COMMIT();

    for (int c = 0; c < NCHUNK; c++) {
        const uint32_t sbuf = sbase + (uint32_t)(c & 1) * STAGE;
        if (c + 1 < NCHUNK) {
            issue_chunk(sbase + (uint32_t)((c + 1) & 1) * STAGE, c + 1, m0, n0, Wh, tid);
            CP_COMMIT();
            CP_WAIT(1);
        } else {
            CP_WAIT(0);
        }
        __syncthreads();

        const uint32_t sAhi = sbuf + T_AHI + (uint32_t)(wm * 64) * RS + laneOff;
        const uint32_t sAlo = sbuf + T_ALO + (uint32_t)(wm * 64) * RS + laneOff;
        const uint32_t sB   = sbuf + T_BHI + (uint32_t)(wn * 32) * RS + laneOff;
#pragma unroll
        for (int ks = 0; ks < 4; ks++) {
            uint32_t bfr[2][4];
#pragma unroll
            for (int p = 0; p < 2; p++)
                ldmx4(bfr[p], sB + (uint32_t)(p * 16) * RS + ks * 32);
#pragma unroll
            for (int mt = 0; mt < 4; mt++) {
                uint32_t a[4];
                ldmx4(a, sAhi + (uint32_t)(mt * 16) * RS + ks * 32);
#pragma unroll
                for (int nt = 0; nt < 4; nt++) {
                    const int p = nt >> 1, s = nt & 1;
                    mma16816h(acc[mt][nt], a, bfr[p][s], bfr[p][s + 2]);
                }
                ldmx4(a, sAlo + (uint32_t)(mt * 16) * RS + ks * 32);
#pragma unroll
                for (int nt = 0; nt < 4; nt++) {
                    const int p = nt >> 1, s = nt & 1;
                    mma16816h(acc[mt][nt], a, bfr[p][s], bfr[p][s + 2]);
                }
            }
        }
        __syncthreads();
    }

    // epilogue: +bias, write f16 hi/lo (Q,K) or f16 (V)
    const int g   = lane >> 2;
    const int tig = lane & 3;
    __half* Oh = (z == 0) ? g_Qh : (z == 1) ? g_Kh : g_Vh;
    __half* Ol = (z == 0) ? g_Ql : g_Kl;   // unused for z==2
#pragma unroll
    for (int mt = 0; mt < 4; mt++) {
        const int rbase = m0 + wm * 64 + mt * 16 + g;
#pragma unroll
        for (int nt = 0; nt < 4; nt++) {
            const int ncol = n0 + wn * 32 + nt * 8 + tig * 2;
            const float b0 = bias[ncol], b1 = bias[ncol + 1];
            float v00 = acc[mt][nt][0] + b0, v01 = acc[mt][nt][1] + b1;
            float v10 = acc[mt][nt][2] + b0, v11 = acc[mt][nt][3] + b1;
            const size_t o0 = (size_t)rbase * E_DIM + ncol;
            const size_t o1 = (size_t)(rbase + 8) * E_DIM + ncol;
            __half h00 = __float2half_rn(v00), h01 = __float2half_rn(v01);
            __half h10 = __float2half_rn(v10), h11 = __float2half_rn(v11);
            *(__half2*)&Oh[o0] = __halves2half2(h00, h01);
            *(__half2*)&Oh[o1] = __halves2half2(h10, h11);
            if (z != 2) {
                *(__half2*)&Ol[o0] = __halves2half2(
                    __float2half_rn(v00 - __half2float(h00)),
                    __float2half_rn(v01 - __half2float(h01)));
                *(__half2*)&Ol[o1] = __halves2half2(
                    __float2half_rn(v10 - __half2float(h10)),
                    __float2half_rn(v11 - __half2float(h11)));
            }
        }
    }
}

// ============================================================================
// Kernel 2: V_total[b,h,d] from f16 V (consistent with PV's f16 quantization).
// grid = 32, 512 threads.
// ============================================================================
__global__ __launch_bounds__(512, 1)
void vtotal_kernel() {
    const int bh = blockIdx.x;
    const __half2* Vb = (const __half2*)(g_Vh) + (size_t)bh * 128 * (E_DIM / 2);
    const int tid = threadIdx.x;
    const int d2 = tid & 31;     // half2 index within 64-elem block
    const int g  = tid >> 5;     // 0..15
    float sx = 0.f, sy = 0.f;
    for (int r = g; r < 128; r += 16) {
        const __half2* row = Vb + (size_t)r * (E_DIM / 2);
#pragma unroll
        for (int cb = 0; cb < 16; cb++) {
            float2 f = __half22float2(row[cb * 32 + d2]);
            sx += f.x; sy += f.y;
        }
    }
    __shared__ float red[16][64];
    red[g][d2 * 2] = sx;
    red[g][d2 * 2 + 1] = sy;
    __syncthreads();
    if (tid < 64) {
        float tt = 0.f;
#pragma unroll
        for (int i2 = 0; i2 < 16; i2++) tt += red[i2][tid];
        g_Vtot[bh * 64 + tid] = tt;
    }
}

// ============================================================================
// Kernel 3: tensor-core windowed attention; all operands pre-converted f16.
//   Loads are pure cp.async: Qhi/Qlo [16][72], Khi/Klo [272][72], V [272][72].
//   QK = Qhi*Khi + Qhi*Klo + Qlo*Khi; P=exp(s)-1 masked -> f16 frags;
//   PV B-frags via ldmatrix.x4.trans on row-major V.
// ============================================================================
#define A_OFF_VT   0
#define A_OFF_DEN  256
#define A_OFF_RS   320
#define A_OFF_QHI  1024
#define A_OFF_QLO  3328
#define A_OFF_KHI  5632
#define A_OFF_KLO  44800
#define A_OFF_VS   83968
#define A_SMEM     123136
#define A_OFF_OP   A_OFF_KHI     // 32KB partials alias Khi after last sync

__device__ __forceinline__ uint32_t packh2(float a, float b) {
    __half2 h = __floats2half2_rn(a, b);
    return *(uint32_t*)&h;
}

__global__ __launch_bounds__(256, 1)
void attn_tc_kernel(float* __restrict__ out) {
    extern __shared__ char dsm[];
    const uint32_t sbase = smem_u32(dsm);
    const int t   = blockIdx.x;
    const int h   = blockIdx.y;
    const int b   = blockIdx.z;
    const int tid = threadIdx.x;
    const int wid = tid >> 5;
    const int lane = tid & 31;

    float* vt  = (float*)(dsm + A_OFF_VT);
    float* den = (float*)(dsm + A_OFF_DEN);
    float* rsp = (float*)(dsm + A_OFF_RS);

    const size_t headrow = (size_t)b * S_LEN + (size_t)h * 128;

    // ---- load phase: pure cp.async ----
    {   // Q hi/lo: 256 units of 16B
        const int tensor = tid >> 7, qi = (tid >> 3) & 15, c = tid & 7;
        const __half* src = (tensor ? g_Ql : g_Qh) + (headrow + t) * E_DIM + qi * 64 + c * 8;
        cp_async16(sbase + (tensor ? A_OFF_QLO : A_OFF_QHI) +
                   (uint32_t)(qi * 144 + c * 16), src);
    }
    if (tid < 64) vt[tid] = g_Vtot[((b * NH) + h) * HD + tid];

    const int r0 = t - 8;
#pragma unroll 4
    for (int rro = 0; rro < 17; rro++) {
        const int rr = r0 + rro;
        const bool ok = (rr >= 0 && rr < 128);
        {   // K hi/lo: 256 units
            const int tensor = tid >> 7, jl16 = (tid >> 3) & 15, c = tid & 7;
            const uint32_t doff = (tensor ? A_OFF_KLO : A_OFF_KHI) +
                                  (uint32_t)((rro * 16 + jl16) * 144 + c * 16);
            if (ok) {
                const __half* src = (tensor ? g_Kl : g_Kh) +
                                    (headrow + rr) * E_DIM + jl16 * 64 + c * 8;
                cp_async16(sbase + doff, src);
            } else {
                *(uint4*)(dsm + doff) = make_uint4(0, 0, 0, 0);
            }
        }
        if (tid < 128) {   // V: 128 units
            const int jl16 = tid >> 3, c = tid & 7;
            const uint32_t doff = A_OFF_VS + (uint32_t)((rro * 16 + jl16) * 144 + c * 16);
            if (ok) {
                const __half* src = g_Vh + (headrow + rr) * E_DIM + jl16 * 64 + c * 8;
                cp_async16(sbase + doff, src);
            } else {
                *(uint4*)(dsm + doff) = make_uint4(0, 0, 0, 0);
            }
        }
    }
    CP_COMMIT();
    CP_WAIT(0);
    __syncthreads();

    // ---- per-warp: QK mma -> exp/mask -> P frags -> PV mma ----
    const int g   = lane >> 2;
    const int tig = lane & 3;
    const uint32_t loQ = sbase + (uint32_t)((lane & 15) * 144 + (lane >> 4) * 16);
    const uint32_t loV = sbase + A_OFF_VS +
                         (uint32_t)((lane & 15) * 144 + (lane >> 4) * 16);
    const int i0 = t * 16 + g, i1 = i0 + 8;
    const int jgbase = r0 * 16;

    float oacc[8][4];
#pragma unroll
    for (int dt = 0; dt < 8; dt++)
#pragma unroll
        for (int j = 0; j < 4; j++) oacc[dt][j] = 0.f;
    float rs0 = 0.f, rs1 = 0.f;

    const int np = (wid == 7) ? 3 : 2;
    for (int pi = 0; pi < np; pi++) {
        const int pr = (pi == 0) ? wid : (pi == 1) ? (wid + 8) : 16;
        float c0[4] = {0.f, 0.f, 0.f, 0.f};
        float c1[4] = {0.f, 0.f, 0.f, 0.f};
#pragma unroll
        for (int ks = 0; ks < 4; ks++) {
            uint32_t ah[4], al[4], kh[4], kl[4];
            ldmx4(ah, loQ + A_OFF_QHI + ks * 32);
            ldmx4(al, loQ + A_OFF_QLO + ks * 32);
            ldmx4(kh, loQ + A_OFF_KHI + (uint32_t)pr * 2304 + ks * 32);
            ldmx4(kl, loQ + A_OFF_KLO + (uint32_t)pr * 2304 + ks * 32);
            mma16816h(c0, ah, kh[0], kh[2]);
            mma16816h(c0, ah, kl[0], kl[2]);
            mma16816h(c0, al, kh[0], kh[2]);
            mma16816h(c1, ah, kh[1], kh[3]);
            mma16816h(c1, ah, kl[1], kl[3]);
            mma16816h(c1, al, kh[1], kh[3]);
        }
        uint32_t pf[4];
#pragma unroll
        for (int s = 0; s < 2; s++) {
            const float* cc = s ? c1 : c0;
            const int jg0 = jgbase + pr * 16 + s * 8 + 2 * tig;
            const int jg1 = jg0 + 1;
            const bool ok0 = (jg0 >= 0) && (jg0 < S_LEN);
            const bool ok1 = (jg1 >= 0) && (jg1 < S_LEN);
            float w00 = (ok0 && jg0 >= i0 - WWIN && jg0 < i0 + WWIN)
                        ? (__expf(cc[0] * 0.125f) - 1.f) : 0.f;
            float w01 = (ok1 && jg1 >= i0 - WWIN && jg1 < i0 + WWIN)
                        ? (__expf(cc[1] * 0.125f) - 1.f) : 0.f;
            float w10 = (ok0 && jg0 >= i1 - WWIN && jg0 < i1 + WWIN)
                        ? (__expf(cc[2] * 0.125f) - 1.f) : 0.f;
            float w11 = (ok1 && jg1 >= i1 - WWIN && jg1 < i1 + WWIN)
                        ? (__expf(cc[3] * 0.125f) - 1.f) : 0.f;
            rs0 += w00 + w01;
            rs1 += w10 + w11;
            pf[s * 2 + 0] = packh2(w00, w01);
            pf[s * 2 + 1] = packh2(w10, w11);
        }
        // PV: B frags from row-major V via ldmatrix.trans
#pragma unroll
        for (int dp = 0; dp < 4; dp++) {
            uint32_t vb[4];
            ldmx4t(vb, loV + (uint32_t)pr * 2304 + dp * 32);
            mma16816h(oacc[dp * 2 + 0], pf, vb[0], vb[1]);
            mma16816h(oacc[dp * 2 + 1], pf, vb[2], vb[3]);
        }
    }

    rs0 += __shfl_xor_sync(0xFFFFFFFF, rs0, 1);
    rs0 += __shfl_xor_sync(0xFFFFFFFF, rs0, 2);
    rs1 += __shfl_xor_sync(0xFFFFFFFF, rs1, 1);
    rs1 += __shfl_xor_sync(0xFFFFFFFF, rs1, 2);
    if (tig == 0) {
        rsp[wid * 16 + g]     = rs0;
        rsp[wid * 16 + g + 8] = rs1;
    }
    __syncthreads();   // all K reads done; op may alias Khi now

    {
        float* op = (float*)(dsm + A_OFF_OP) + wid * 1024;
#pragma unroll
        for (int dt = 0; dt < 8; dt++) {
            *(float2*)&op[g * 64 + dt * 8 + 2 * tig] =
                make_float2(oacc[dt][0], oacc[dt][1]);
            *(float2*)&op[(g + 8) * 64 + dt * 8 + 2 * tig] =
                make_float2(oacc[dt][2], oacc[dt][3]);
        }
    }
    if (tid < 16) {
        float s = 0.f;
#pragma unroll
        for (int w8 = 0; w8 < 8; w8++) s += rsp[w8 * 16 + tid];
        den[tid] = (float)S_LEN + s;
    }
    __syncthreads();

    {
        const int qi = tid >> 4;
        const int dc = tid & 15;
        const float* opf = (const float*)(dsm + A_OFF_OP);
        float4 sum = *(const float4*)&vt[dc * 4];
#pragma unroll
        for (int w8 = 0; w8 < 8; w8++) {
            const float4 o = *(const float4*)&opf[w8 * 1024 + qi * 64 + dc * 4];
            sum.x += o.x; sum.y += o.y; sum.z += o.z; sum.w += o.w;
        }
        const float inv = 1.0f / den[qi];
        sum.x *= inv; sum.y *= inv; sum.z *= inv; sum.w *= inv;
        const int i = t * 16 + qi;
        *(float4*)&out[((size_t)b * S_LEN + i) * E_DIM + h * HD + dc * 4] = sum;
    }
}

// ============================================================================
// kernel_launch
// ============================================================================
extern "C" void kernel_launch(void* const* d_in, const int* in_sizes, int n_in,
                              void* d_out, int out_size) {
    (void)in_sizes; (void)n_in; (void)out_size;
    const float* x  = (const float*)d_in[0];
    const float* Wq = (const float*)d_in[1];
    const float* bq = (const float*)d_in[2];
    const float* Wk = (const float*)d_in[3];
    const float* bk = (const float*)d_in[4];
    const float* Wv = (const float*)d_in[5];
    const float* bv = (const float*)d_in[6];
    float* out = (float*)d_out;

    split_f16_kernel<<<(M_TOT * E_DIM / 4 + 255) / 256, 256>>>(x, 0, M_TOT * E_DIM / 4);
    split_f16_kernel<<<(E_DIM * E_DIM / 4 + 255) / 256, 256>>>(Wq, 1, E_DIM * E_DIM / 4);
    split_f16_kernel<<<(E_DIM * E_DIM / 4 + 255) / 256, 256>>>(Wk, 2, E_DIM * E_DIM / 4);
    split_f16_kernel<<<(E_DIM * E_DIM / 4 + 255) / 256, 256>>>(Wv, 3, E_DIM * E_DIM / 4);

    cudaFuncSetAttribute(hmma_gemm_kernel, cudaFuncAttributeMaxDynamicSharedMemorySize,
                         GEMM_SMEM);
    dim3 gg(E_DIM / 128, M_TOT / 128, 3);
    hmma_gemm_kernel<<<gg, 256, GEMM_SMEM>>>(bq, bk, bv);

    vtotal_kernel<<<BATCH * NH, 512>>>();

    cudaFuncSetAttribute(attn_tc_kernel, cudaFuncAttributeMaxDynamicSharedMemorySize,
                         A_SMEM);
    dim3 g3(128, NH, BATCH);
    attn_tc_kernel<<<g3, 256, A_SMEM>>>(out);
}

// round 12
// speedup vs baseline: 3.5837x; 1.4707x over previous
#include <cuda_runtime.h>
#include <cuda_fp16.h>
#include <cstdint>

#define S_LEN 2048
#define E_DIM 1024
#define NH    16
#define HD    64
#define WWIN  128
#define BATCH 2
#define M_TOT (BATCH * S_LEN)   // 4096

// ---------------- scratch (device globals; no allocations allowed) ----------------
__device__ float g_Vtot[BATCH * NH * HD];
__device__ __half g_Xh16[M_TOT * E_DIM];
__device__ __half g_Wh16[3 * E_DIM * E_DIM];
// GEMM outputs, pre-split for attention
__device__ __half g_Qh[M_TOT * E_DIM];
__device__ __half g_Ql[M_TOT * E_DIM];
__device__ __half g_Kh[M_TOT * E_DIM];
__device__ __half g_Kl[M_TOT * E_DIM];
__device__ __half g_Vh[M_TOT * E_DIM];

// ---------------- PTX helpers (baseline ISA only) ----------------
__device__ __forceinline__ uint32_t smem_u32(const void* p) {
    uint32_t a;
    asm("{ .reg .u64 t; cvta.to.shared.u64 t, %1; cvt.u32.u64 %0, t; }" : "=r"(a) : "l"(p));
    return a;
}
__device__ __forceinline__ void cp_async16(uint32_t s, const void* g) {
    asm volatile("cp.async.cg.shared.global [%0], [%1], 16;" :: "r"(s), "l"(g) : "memory");
}
#define CP_COMMIT() asm volatile("cp.async.commit_group;" ::: "memory")
#define CP_WAIT(n)  asm volatile("cp.async.wait_group %0;" :: "n"(n) : "memory")

__device__ __forceinline__ void ldmx4(uint32_t r[4], uint32_t addr) {
    asm volatile("ldmatrix.sync.aligned.m8n8.x4.shared.b16 {%0,%1,%2,%3}, [%4];"
                 : "=r"(r[0]), "=r"(r[1]), "=r"(r[2]), "=r"(r[3]) : "r"(addr));
}
__device__ __forceinline__ void ldmx4t(uint32_t r[4], uint32_t addr) {
    asm volatile("ldmatrix.sync.aligned.m8n8.x4.trans.shared.b16 {%0,%1,%2,%3}, [%4];"
                 : "=r"(r[0]), "=r"(r[1]), "=r"(r[2]), "=r"(r[3]) : "r"(addr));
}
__device__ __forceinline__ void mma16816h(float c[4], const uint32_t a[4],
                                          uint32_t b0, uint32_t b1) {
    asm volatile(
        "mma.sync.aligned.m16n8k16.row.col.f32.f16.f16.f32 "
        "{%0,%1,%2,%3}, {%4,%5,%6,%7}, {%8,%9}, {%0,%1,%2,%3};"
        : "+f"(c[0]), "+f"(c[1]), "+f"(c[2]), "+f"(c[3])
        : "r"(a[0]), "r"(a[1]), "r"(a[2]), "r"(a[3]), "r"(b0), "r"(b1));
}

// ============================================================================
// Kernel 0: merged fp32 -> f16 convert for X, Wq, Wk, Wv (single launch).
// Exactly (M_TOT*E_DIM + 3*E_DIM*E_DIM)/4 = 1835008 quads = 7168 blocks x 256.
// ============================================================================
#define XQ (M_TOT * E_DIM / 4)      // 1048576
#define WQ (E_DIM * E_DIM / 4)      // 262144
#define SPLIT_BLOCKS ((XQ + 3 * WQ) / 256)   // 7168

__global__ __launch_bounds__(256, 8)
void split_all_kernel(const float* __restrict__ x, const float* __restrict__ wq,
                      const float* __restrict__ wk, const float* __restrict__ wv) {
    const int i = blockIdx.x * 256 + threadIdx.x;
    const float* src;
    __half2* dst;
    int k;
    if (i < XQ) {
        src = x; k = i; dst = (__half2*)g_Xh16;
    } else {
        const int j = i - XQ;
        const int w = j / WQ;
        k = j - w * WQ;
        src = (w == 0) ? wq : (w == 1) ? wk : wv;
        dst = (__half2*)(g_Wh16 + (size_t)w * E_DIM * E_DIM);
    }
    float4 v = ((const float4*)src)[k];
    dst[2 * k]     = __floats2half2_rn(v.x, v.y);
    dst[2 * k + 1] = __floats2half2_rn(v.z, v.w);
}

// ============================================================================
// Kernel 1: single-product f16 GEMM via mma.sync.
//   Out = X16 @ W16.T + b   (error = x,W f16 quantization)
// BM=BN=128, KC=64, cp.async double buffer, 8 warps of 64x32, 2 CTAs/SM.
// Epilogue writes f16 hi/lo (Q,K) or f16 (V).
// ============================================================================
#define KC 64
#define NCHUNK (E_DIM / KC)
#define RS 144
#define T_A 0
#define T_B 18432
#define STAGE 36864
#define GEMM_SMEM (2 * STAGE)   // 73728 -> 2 CTAs/SM

__device__ __forceinline__ void issue_chunk(uint32_t sdst, int kc, int m0, int n0,
                                            const __half* Wh, int tid) {
#pragma unroll
    for (int t4 = 0; t4 < 4; t4++) {
        const int idx = tid + t4 * 256;
        const int r = idx >> 3, c = idx & 7;
        const uint32_t so = (uint32_t)(r * RS + c * 16);
        cp_async16(sdst + T_A + so,
                   g_Xh16 + (size_t)(m0 + r) * E_DIM + kc * KC + c * 8);
        cp_async16(sdst + T_B + so,
                   Wh + (size_t)(n0 + r) * E_DIM + kc * KC + c * 8);
    }
}

__global__ __launch_bounds__(256, 2)
void hmma_gemm_kernel(const float* __restrict__ bq, const float* __restrict__ bk,
                      const float* __restrict__ bv) {
    extern __shared__ char dsm[];
    const uint32_t sbase = smem_u32(dsm);
    const int tid  = threadIdx.x;
    const int wid  = tid >> 5;
    const int lane = tid & 31;
    const int n0 = blockIdx.x * 128;
    const int m0 = blockIdx.y * 128;
    const int z  = blockIdx.z;

    const __half* Wh = g_Wh16 + (size_t)z * E_DIM * E_DIM;
    const float* bias = (z == 0) ? bq : (z == 1) ? bk : bv;

    const int wm = wid & 1;
    const int wn = wid >> 1;

    float acc[4][4][4];
#pragma unroll
    for (int mt = 0; mt < 4; mt++)
#pragma unroll
        for (int nt = 0; nt < 4; nt++)
#pragma unroll
            for (int j = 0; j < 4; j++) acc[mt][nt][j] = 0.f;

    const uint32_t laneOff = (uint32_t)((lane & 15) * RS + (lane >> 4) * 16);

    issue_chunk(sbase, 0, m0, n0, Wh, tid);
    CP_COMMIT();

    for (int c = 0; c < NCHUNK; c++) {
        const uint32_t sbuf = sbase + (uint32_t)(c & 1) * STAGE;
        if (c + 1 < NCHUNK) {
            issue_chunk(sbase + (uint32_t)((c + 1) & 1) * STAGE, c + 1, m0, n0, Wh, tid);
            CP_COMMIT();
            CP_WAIT(1);
        } else {
            CP_WAIT(0);
        }
        __syncthreads();

        const uint32_t sA = sbuf + T_A + (uint32_t)(wm * 64) * RS + laneOff;
        const uint32_t sB = sbuf + T_B + (uint32_t)(wn * 32) * RS + laneOff;
#pragma unroll
        for (int ks = 0; ks < 4; ks++) {
            uint32_t bfr[2][4];
#pragma unroll
            for (int p = 0; p < 2; p++)
                ldmx4(bfr[p], sB + (uint32_t)(p * 16) * RS + ks * 32);
#pragma unroll
            for (int mt = 0; mt < 4; mt++) {
                uint32_t a[4];
                ldmx4(a, sA + (uint32_t)(mt * 16) * RS + ks * 32);
#pragma unroll
                for (int nt = 0; nt < 4; nt++) {
                    const int p = nt >> 1, s = nt & 1;
                    mma16816h(acc[mt][nt], a, bfr[p][s], bfr[p][s + 2]);
                }
            }
        }
        __syncthreads();
    }

    // epilogue: +bias, write f16 hi/lo (Q,K) or f16 (V)
    const int g   = lane >> 2;
    const int tig = lane & 3;
    __half* Oh = (z == 0) ? g_Qh : (z == 1) ? g_Kh : g_Vh;
    __half* Ol = (z == 0) ? g_Ql : g_Kl;   // unused for z==2
#pragma unroll
    for (int mt = 0; mt < 4; mt++) {
        const int rbase = m0 + wm * 64 + mt * 16 + g;
#pragma unroll
        for (int nt = 0; nt < 4; nt++) {
            const int ncol = n0 + wn * 32 + nt * 8 + tig * 2;
            const float b0 = bias[ncol], b1 = bias[ncol + 1];
            float v00 = acc[mt][nt][0] + b0, v01 = acc[mt][nt][1] + b1;
            float v10 = acc[mt][nt][2] + b0, v11 = acc[mt][nt][3] + b1;
            const size_t o0 = (size_t)rbase * E_DIM + ncol;
            const size_t o1 = (size_t)(rbase + 8) * E_DIM + ncol;
            __half h00 = __float2half_rn(v00), h01 = __float2half_rn(v01);
            __half h10 = __float2half_rn(v10), h11 = __float2half_rn(v11);
            *(__half2*)&Oh[o0] = __halves2half2(h00, h01);
            *(__half2*)&Oh[o1] = __halves2half2(h10, h11);
            if (z != 2) {
                *(__half2*)&Ol[o0] = __halves2half2(
                    __float2half_rn(v00 - __half2float(h00)),
                    __float2half_rn(v01 - __half2float(h01)));
                *(__half2*)&Ol[o1] = __halves2half2(
                    __float2half_rn(v10 - __half2float(h10)),
                    __float2half_rn(v11 - __half2float(h11)));
            }
        }
    }
}

// ============================================================================
// Kernel 2: V_total[b,h,d] from f16 V.
// ============================================================================
__global__ __launch_bounds__(512, 1)
void vtotal_kernel() {
    const int bh = blockIdx.x;
    const __half2* Vb = (const __half2*)(g_Vh) + (size_t)bh * 128 * (E_DIM / 2);
    const int tid = threadIdx.x;
    const int d2 = tid & 31;
    const int g  = tid >> 5;
    float sx = 0.f, sy = 0.f;
    for (int r = g; r < 128; r += 16) {
        const __half2* row = Vb + (size_t)r * (E_DIM / 2);
#pragma unroll
        for (int cb = 0; cb < 16; cb++) {
            float2 f = __half22float2(row[cb * 32 + d2]);
            sx += f.x; sy += f.y;
        }
    }
    __shared__ float red[16][64];
    red[g][d2 * 2] = sx;
    red[g][d2 * 2 + 1] = sy;
    __syncthreads();
    if (tid < 64) {
        float tt = 0.f;
#pragma unroll
        for (int i2 = 0; i2 < 16; i2++) tt += red[i2][tid];
        g_Vtot[bh * 64 + tid] = tt;
    }
}

// ============================================================================
// Kernel 3: tensor-core windowed attention (unchanged from R8-pass).
// ============================================================================
#define A_OFF_VT   0
#define A_OFF_DEN  256
#define A_OFF_RS   320
#define A_OFF_QHI  1024
#define A_OFF_QLO  3328
#define A_OFF_KHI  5632
#define A_OFF_KLO  44800
#define A_OFF_VS   83968
#define A_SMEM     123136
#define A_OFF_OP   A_OFF_KHI     // 32KB partials alias Khi after last sync

__device__ __forceinline__ uint32_t packh2(float a, float b) {
    __half2 h = __floats2half2_rn(a, b);
    return *(uint32_t*)&h;
}

__global__ __launch_bounds__(256, 1)
void attn_tc_kernel(float* __restrict__ out) {
    extern __shared__ char dsm[];
    const uint32_t sbase = smem_u32(dsm);
    const int t   = blockIdx.x;
    const int h   = blockIdx.y;
    const int b   = blockIdx.z;
    const int tid = threadIdx.x;
    const int wid = tid >> 5;
    const int lane = tid & 31;

    float* vt  = (float*)(dsm + A_OFF_VT);
    float* den = (float*)(dsm + A_OFF_DEN);
    float* rsp = (float*)(dsm + A_OFF_RS);

    const size_t headrow = (size_t)b * S_LEN + (size_t)h * 128;

    // ---- load phase: pure cp.async ----
    {
        const int tensor = tid >> 7, qi = (tid >> 3) & 15, c = tid & 7;
        const __half* src = (tensor ? g_Ql : g_Qh) + (headrow + t) * E_DIM + qi * 64 + c * 8;
        cp_async16(sbase + (tensor ? A_OFF_QLO : A_OFF_QHI) +
                   (uint32_t)(qi * 144 + c * 16), src);
    }
    if (tid < 64) vt[tid] = g_Vtot[((b * NH) + h) * HD + tid];

    const int r0 = t - 8;
#pragma unroll 4
    for (int rro = 0; rro < 17; rro++) {
        const int rr = r0 + rro;
        const bool ok = (rr >= 0 && rr < 128);
        {
            const int tensor = tid >> 7, jl16 = (tid >> 3) & 15, c = tid & 7;
            const uint32_t doff = (tensor ? A_OFF_KLO : A_OFF_KHI) +
                                  (uint32_t)((rro * 16 + jl16) * 144 + c * 16);
            if (ok) {
                const __half* src = (tensor ? g_Kl : g_Kh) +
                                    (headrow + rr) * E_DIM + jl16 * 64 + c * 8;
                cp_async16(sbase + doff, src);
            } else {
                *(uint4*)(dsm + doff) = make_uint4(0, 0, 0, 0);
            }
        }
        if (tid < 128) {
            const int jl16 = tid >> 3, c = tid & 7;
            const uint32_t doff = A_OFF_VS + (uint32_t)((rro * 16 + jl16) * 144 + c * 16);
            if (ok) {
                const __half* src = g_Vh + (headrow + rr) * E_DIM + jl16 * 64 + c * 8;
                cp_async16(sbase + doff, src);
            } else {
                *(uint4*)(dsm + doff) = make_uint4(0, 0, 0, 0);
            }
        }
    }
    CP_COMMIT();
    CP_WAIT(0);
    __syncthreads();

    // ---- per-warp: QK mma -> exp/mask -> P frags -> PV mma ----
    const int g   = lane >> 2;
    const int tig = lane & 3;
    const uint32_t loQ = sbase + (uint32_t)((lane & 15) * 144 + (lane >> 4) * 16);
    const uint32_t loV = sbase + A_OFF_VS +
                         (uint32_t)((lane & 15) * 144 + (lane >> 4) * 16);
    const int i0 = t * 16 + g, i1 = i0 + 8;
    const int jgbase = r0 * 16;

    float oacc[8][4];
#pragma unroll
    for (int dt = 0; dt < 8; dt++)
#pragma unroll
        for (int j = 0; j < 4; j++) oacc[dt][j] = 0.f;
    float rs0 = 0.f, rs1 = 0.f;

    const int np = (wid == 7) ? 3 : 2;
    for (int pi = 0; pi < np; pi++) {
        const int pr = (pi == 0) ? wid : (pi == 1) ? (wid + 8) : 16;
        float c0[4] = {0.f, 0.f, 0.f, 0.f};
        float c1[4] = {0.f, 0.f, 0.f, 0.f};
#pragma unroll
        for (int ks = 0; ks < 4; ks++) {
            uint32_t ah[4], al[4], kh[4], kl[4];
            ldmx4(ah, loQ + A_OFF_QHI + ks * 32);
            ldmx4(al, loQ + A_OFF_QLO + ks * 32);
            ldmx4(kh, loQ + A_OFF_KHI + (uint32_t)pr * 2304 + ks * 32);
            ldmx4(kl, loQ + A_OFF_KLO + (uint32_t)pr * 2304 + ks * 32);
            mma16816h(c0, ah, kh[0], kh[2]);
            mma16816h(c0, ah, kl[0], kl[2]);
            mma16816h(c0, al, kh[0], kh[2]);
            mma16816h(c1, ah, kh[1], kh[3]);
            mma16816h(c1, ah, kl[1], kl[3]);
            mma16816h(c1, al, kh[1], kh[3]);
        }
        uint32_t pf[4];
#pragma unroll
        for (int s = 0; s < 2; s++) {
            const float* cc = s ? c1 : c0;
            const int jg0 = jgbase + pr * 16 + s * 8 + 2 * tig;
            const int jg1 = jg0 + 1;
            const bool ok0 = (jg0 >= 0) && (jg0 < S_LEN);
            const bool ok1 = (jg1 >= 0) && (jg1 < S_LEN);
            float w00 = (ok0 && jg0 >= i0 - WWIN && jg0 < i0 + WWIN)
                        ? (__expf(cc[0] * 0.125f) - 1.f) : 0.f;
            float w01 = (ok1 && jg1 >= i0 - WWIN && jg1 < i0 + WWIN)
                        ? (__expf(cc[1] * 0.125f) - 1.f) : 0.f;
            float w10 = (ok0 && jg0 >= i1 - WWIN && jg0 < i1 + WWIN)
                        ? (__expf(cc[2] * 0.125f) - 1.f) : 0.f;
            float w11 = (ok1 && jg1 >= i1 - WWIN && jg1 < i1 + WWIN)
                        ? (__expf(cc[3] * 0.125f) - 1.f) : 0.f;
            rs0 += w00 + w01;
            rs1 += w10 + w11;
            pf[s * 2 + 0] = packh2(w00, w01);
            pf[s * 2 + 1] = packh2(w10, w11);
        }
#pragma unroll
        for (int dp = 0; dp < 4; dp++) {
            uint32_t vb[4];
            ldmx4t(vb, loV + (uint32_t)pr * 2304 + dp * 32);
            mma16816h(oacc[dp * 2 + 0], pf, vb[0], vb[1]);
            mma16816h(oacc[dp * 2 + 1], pf, vb[2], vb[3]);
        }
    }

    rs0 += __shfl_xor_sync(0xFFFFFFFF, rs0, 1);
    rs0 += __shfl_xor_sync(0xFFFFFFFF, rs0, 2);
    rs1 += __shfl_xor_sync(0xFFFFFFFF, rs1, 1);
    rs1 += __shfl_xor_sync(0xFFFFFFFF, rs1, 2);
    if (tig == 0) {
        rsp[wid * 16 + g]     = rs0;
        rsp[wid * 16 + g + 8] = rs1;
    }
    __syncthreads();   // all K reads done; op may alias Khi now

    {
        float* op = (float*)(dsm + A_OFF_OP) + wid * 1024;
#pragma unroll
        for (int dt = 0; dt < 8; dt++) {
            *(float2*)&op[g * 64 + dt * 8 + 2 * tig] =
                make_float2(oacc[dt][0], oacc[dt][1]);
            *(float2*)&op[(g + 8) * 64 + dt * 8 + 2 * tig] =
                make_float2(oacc[dt][2], oacc[dt][3]);
        }
    }
    if (tid < 16) {
        float s = 0.f;
#pragma unroll
        for (int w8 = 0; w8 < 8; w8++) s += rsp[w8 * 16 + tid];
        den[tid] = (float)S_LEN + s;
    }
    __syncthreads();

    {
        const int qi = tid >> 4;
        const int dc = tid & 15;
        const float* opf = (const float*)(dsm + A_OFF_OP);
        float4 sum = *(const float4*)&vt[dc * 4];
#pragma unroll
        for (int w8 = 0; w8 < 8; w8++) {
            const float4 o = *(const float4*)&opf[w8 * 1024 + qi * 64 + dc * 4];
            sum.x += o.x; sum.y += o.y; sum.z += o.z; sum.w += o.w;
        }
        const float inv = 1.0f / den[qi];
        sum.x *= inv; sum.y *= inv; sum.z *= inv; sum.w *= inv;
        const int i = t * 16 + qi;
        *(float4*)&out[((size_t)b * S_LEN + i) * E_DIM + h * HD + dc * 4] = sum;
    }
}

// ============================================================================
// kernel_launch
// ============================================================================
extern "C" void kernel_launch(void* const* d_in, const int* in_sizes, int n_in,
                              void* d_out, int out_size) {
    (void)in_sizes; (void)n_in; (void)out_size;
    const float* x  = (const float*)d_in[0];
    const float* Wq = (const float*)d_in[1];
    const float* bq = (const float*)d_in[2];
    const float* Wk = (const float*)d_in[3];
    const float* bk = (const float*)d_in[4];
    const float* Wv = (const float*)d_in[5];
    const float* bv = (const float*)d_in[6];
    float* out = (float*)d_out;

    split_all_kernel<<<SPLIT_BLOCKS, 256>>>(x, Wq, Wk, Wv);

    cudaFuncSetAttribute(hmma_gemm_kernel, cudaFuncAttributeMaxDynamicSharedMemorySize,
                         GEMM_SMEM);
    dim3 gg(E_DIM / 128, M_TOT / 128, 3);
    hmma_gemm_kernel<<<gg, 256, GEMM_SMEM>>>(bq, bk, bv);

    vtotal_kernel<<<BATCH * NH, 512>>>();

    cudaFuncSetAttribute(attn_tc_kernel, cudaFuncAttributeMaxDynamicSharedMemorySize,
                         A_SMEM);
    dim3 g3(128, NH, BATCH);
    attn_tc_kernel<<<g3, 256, A_SMEM>>>(out);
}

// round 13
// speedup vs baseline: 4.8094x; 1.3420x over previous
#include <cuda_runtime.h>
#include <cuda_fp16.h>
#include <cstdint>

#define S_LEN 2048
#define E_DIM 1024
#define NH    16
#define HD    64
#define WWIN  128
#define BATCH 2
#define M_TOT (BATCH * S_LEN)   // 4096

// ---------------- scratch (device globals; no allocations allowed) ----------------
__device__ float g_Vtot[BATCH * NH * HD];
__device__ __half g_Xh16[M_TOT * E_DIM];
__device__ __half g_Wh16[3 * E_DIM * E_DIM];
__device__ __half g_Q16[M_TOT * E_DIM];
__device__ __half g_K16[M_TOT * E_DIM];
__device__ __half g_V16[M_TOT * E_DIM];

// ---------------- PTX helpers (baseline ISA only) ----------------
__device__ __forceinline__ uint32_t smem_u32(const void* p) {
    uint32_t a;
    asm("{ .reg .u64 t; cvta.to.shared.u64 t, %1; cvt.u32.u64 %0, t; }" : "=r"(a) : "l"(p));
    return a;
}
__device__ __forceinline__ void cp_async16(uint32_t s, const void* g) {
    asm volatile("cp.async.cg.shared.global [%0], [%1], 16;" :: "r"(s), "l"(g) : "memory");
}
#define CP_COMMIT() asm volatile("cp.async.commit_group;" ::: "memory")
#define CP_WAIT(n)  asm volatile("cp.async.wait_group %0;" :: "n"(n) : "memory")

__device__ __forceinline__ void ldmx4(uint32_t r[4], uint32_t addr) {
    asm volatile("ldmatrix.sync.aligned.m8n8.x4.shared.b16 {%0,%1,%2,%3}, [%4];"
                 : "=r"(r[0]), "=r"(r[1]), "=r"(r[2]), "=r"(r[3]) : "r"(addr));
}
__device__ __forceinline__ void ldmx4t(uint32_t r[4], uint32_t addr) {
    asm volatile("ldmatrix.sync.aligned.m8n8.x4.trans.shared.b16 {%0,%1,%2,%3}, [%4];"
                 : "=r"(r[0]), "=r"(r[1]), "=r"(r[2]), "=r"(r[3]) : "r"(addr));
}
__device__ __forceinline__ void mma16816h(float c[4], const uint32_t a[4],
                                          uint32_t b0, uint32_t b1) {
    asm volatile(
        "mma.sync.aligned.m16n8k16.row.col.f32.f16.f16.f32 "
        "{%0,%1,%2,%3}, {%4,%5,%6,%7}, {%8,%9}, {%0,%1,%2,%3};"
        : "+f"(c[0]), "+f"(c[1]), "+f"(c[2]), "+f"(c[3])
        : "r"(a[0]), "r"(a[1]), "r"(a[2]), "r"(a[3]), "r"(b0), "r"(b1));
}

// ============================================================================
// Kernel 0: merged fp32 -> f16 convert for X, Wq, Wk, Wv (single launch).
// ============================================================================
#define XQ (M_TOT * E_DIM / 4)      // 1048576
#define WQ (E_DIM * E_DIM / 4)      // 262144
#define SPLIT_BLOCKS ((XQ + 3 * WQ) / 256)   // 7168

__global__ __launch_bounds__(256, 8)
void split_all_kernel(const float* __restrict__ x, const float* __restrict__ wq,
                      const float* __restrict__ wk, const float* __restrict__ wv) {
    const int i = blockIdx.x * 256 + threadIdx.x;
    const float* src;
    __half2* dst;
    int k;
    if (i < XQ) {
        src = x; k = i; dst = (__half2*)g_Xh16;
    } else {
        const int j = i - XQ;
        const int w = j / WQ;
        k = j - w * WQ;
        src = (w == 0) ? wq : (w == 1) ? wk : wv;
        dst = (__half2*)(g_Wh16 + (size_t)w * E_DIM * E_DIM);
    }
    float4 v = ((const float4*)src)[k];
    dst[2 * k]     = __floats2half2_rn(v.x, v.y);
    dst[2 * k + 1] = __floats2half2_rn(v.z, v.w);
}

// ============================================================================
// Kernel 1: single-product f16 GEMM via mma.sync.
//   Out = X16 @ W16.T + b.   Epilogue writes single f16 per output.
// BM=BN=128, KC=64, cp.async double buffer, 8 warps of 64x32, 2 CTAs/SM.
// ============================================================================
#define KC 64
#define NCHUNK (E_DIM / KC)
#define RS 144
#define T_A 0
#define T_B 18432
#define STAGE 36864
#define GEMM_SMEM (2 * STAGE)   // 73728 -> 2 CTAs/SM

__device__ __forceinline__ void issue_chunk(uint32_t sdst, int kc, int m0, int n0,
                                            const __half* Wh, int tid) {
#pragma unroll
    for (int t4 = 0; t4 < 4; t4++) {
        const int idx = tid + t4 * 256;
        const int r = idx >> 3, c = idx & 7;
        const uint32_t so = (uint32_t)(r * RS + c * 16);
        cp_async16(sdst + T_A + so,
                   g_Xh16 + (size_t)(m0 + r) * E_DIM + kc * KC + c * 8);
        cp_async16(sdst + T_B + so,
                   Wh + (size_t)(n0 + r) * E_DIM + kc * KC + c * 8);
    }
}

__global__ __launch_bounds__(256, 2)
void hmma_gemm_kernel(const float* __restrict__ bq, const float* __restrict__ bk,
                      const float* __restrict__ bv) {
    extern __shared__ char dsm[];
    const uint32_t sbase = smem_u32(dsm);
    const int tid  = threadIdx.x;
    const int wid  = tid >> 5;
    const int lane = tid & 31;
    const int n0 = blockIdx.x * 128;
    const int m0 = blockIdx.y * 128;
    const int z  = blockIdx.z;

    const __half* Wh = g_Wh16 + (size_t)z * E_DIM * E_DIM;
    const float* bias = (z == 0) ? bq : (z == 1) ? bk : bv;

    const int wm = wid & 1;
    const int wn = wid >> 1;

    float acc[4][4][4];
#pragma unroll
    for (int mt = 0; mt < 4; mt++)
#pragma unroll
        for (int nt = 0; nt < 4; nt++)
#pragma unroll
            for (int j = 0; j < 4; j++) acc[mt][nt][j] = 0.f;

    const uint32_t laneOff = (uint32_t)((lane & 15) * RS + (lane >> 4) * 16);

    issue_chunk(sbase, 0, m0, n0, Wh, tid);
    CP_COMMIT();

    for (int c = 0; c < NCHUNK; c++) {
        const uint32_t sbuf = sbase + (uint32_t)(c & 1) * STAGE;
        if (c + 1 < NCHUNK) {
            issue_chunk(sbase + (uint32_t)((c + 1) & 1) * STAGE, c + 1, m0, n0, Wh, tid);
            CP_COMMIT();
            CP_WAIT(1);
        } else {
            CP_WAIT(0);
        }
        __syncthreads();

        const uint32_t sA = sbuf + T_A + (uint32_t)(wm * 64) * RS + laneOff;
        const uint32_t sB = sbuf + T_B + (uint32_t)(wn * 32) * RS + laneOff;
#pragma unroll
        for (int ks = 0; ks < 4; ks++) {
            uint32_t bfr[2][4];
#pragma unroll
            for (int p = 0; p < 2; p++)
                ldmx4(bfr[p], sB + (uint32_t)(p * 16) * RS + ks * 32);
#pragma unroll
            for (int mt = 0; mt < 4; mt++) {
                uint32_t a[4];
                ldmx4(a, sA + (uint32_t)(mt * 16) * RS + ks * 32);
#pragma unroll
                for (int nt = 0; nt < 4; nt++) {
                    const int p = nt >> 1, s = nt & 1;
                    mma16816h(acc[mt][nt], a, bfr[p][s], bfr[p][s + 2]);
                }
            }
        }
        __syncthreads();
    }

    // epilogue: +bias, write f16
    const int g   = lane >> 2;
    const int tig = lane & 3;
    __half* Oh = (z == 0) ? g_Q16 : (z == 1) ? g_K16 : g_V16;
#pragma unroll
    for (int mt = 0; mt < 4; mt++) {
        const int rbase = m0 + wm * 64 + mt * 16 + g;
#pragma unroll
        for (int nt = 0; nt < 4; nt++) {
            const int ncol = n0 + wn * 32 + nt * 8 + tig * 2;
            const float b0 = bias[ncol], b1 = bias[ncol + 1];
            *(__half2*)&Oh[(size_t)rbase * E_DIM + ncol] =
                __floats2half2_rn(acc[mt][nt][0] + b0, acc[mt][nt][1] + b1);
            *(__half2*)&Oh[(size_t)(rbase + 8) * E_DIM + ncol] =
                __floats2half2_rn(acc[mt][nt][2] + b0, acc[mt][nt][3] + b1);
        }
    }
}

// ============================================================================
// Kernel 2: V_total[b,h,d] from f16 V.
// ============================================================================
__global__ __launch_bounds__(512, 1)
void vtotal_kernel() {
    const int bh = blockIdx.x;
    const __half2* Vb = (const __half2*)(g_V16) + (size_t)bh * 128 * (E_DIM / 2);
    const int tid = threadIdx.x;
    const int d2 = tid & 31;
    const int g  = tid >> 5;
    float sx = 0.f, sy = 0.f;
    for (int r = g; r < 128; r += 16) {
        const __half2* row = Vb + (size_t)r * (E_DIM / 2);
#pragma unroll
        for (int cb = 0; cb < 16; cb++) {
            float2 f = __half22float2(row[cb * 32 + d2]);
            sx += f.x; sy += f.y;
        }
    }
    __shared__ float red[16][64];
    red[g][d2 * 2] = sx;
    red[g][d2 * 2 + 1] = sy;
    __syncthreads();
    if (tid < 64) {
        float tt = 0.f;
#pragma unroll
        for (int i2 = 0; i2 < 16; i2++) tt += red[i2][tid];
        g_Vtot[bh * 64 + tid] = tt;
    }
}

// ============================================================================
// Kernel 3: tensor-core windowed attention, single-f16 Q/K/V.
//   Q [16][72], K [272][72], V [272][72] in smem (~80KB) -> 2 CTAs/SM.
//   QK = 1 combo; Q frags hoisted per warp.  P=exp(s)-1 masked -> f16 frags;
//   PV via ldmatrix.x4.trans.  out = (Vtot + P@V)/(2048 + rowsum(P)).
// ============================================================================
#define A_OFF_VT   0
#define A_OFF_DEN  256
#define A_OFF_RS   320
#define A_OFF_Q    1024
#define A_OFF_K    3328
#define A_OFF_V    42496
#define A_SMEM     81664
#define A_OFF_OP   A_OFF_K     // 32KB partials alias K after last sync

__device__ __forceinline__ uint32_t packh2(float a, float b) {
    __half2 h = __floats2half2_rn(a, b);
    return *(uint32_t*)&h;
}

__global__ __launch_bounds__(256, 2)
void attn_tc_kernel(float* __restrict__ out) {
    extern __shared__ char dsm[];
    const uint32_t sbase = smem_u32(dsm);
    const int t   = blockIdx.x;
    const int h   = blockIdx.y;
    const int b   = blockIdx.z;
    const int tid = threadIdx.x;
    const int wid = tid >> 5;
    const int lane = tid & 31;

    float* vt  = (float*)(dsm + A_OFF_VT);
    float* den = (float*)(dsm + A_OFF_DEN);
    float* rsp = (float*)(dsm + A_OFF_RS);

    const size_t headrow = (size_t)b * S_LEN + (size_t)h * 128;

    // ---- load phase: pure cp.async ----
    if (tid < 128) {   // Q: 128 units of 16B
        const int qi = tid >> 3, c = tid & 7;
        cp_async16(sbase + A_OFF_Q + (uint32_t)(qi * 144 + c * 16),
                   g_Q16 + (headrow + t) * E_DIM + qi * 64 + c * 8);
    }
    if (tid < 64) vt[tid] = g_Vtot[((b * NH) + h) * HD + tid];

    const int r0 = t - 8;
#pragma unroll 4
    for (int rro = 0; rro < 17; rro++) {
        const int rr = r0 + rro;
        const bool ok = (rr >= 0 && rr < 128);
        const int half = tid >> 7;          // 0: K, 1: V
        const int jl16 = (tid >> 3) & 15, c = tid & 7;
        const uint32_t doff = (half ? A_OFF_V : A_OFF_K) +
                              (uint32_t)((rro * 16 + jl16) * 144 + c * 16);
        if (ok) {
            const __half* src = (half ? g_V16 : g_K16) +
                                (headrow + rr) * E_DIM + jl16 * 64 + c * 8;
            cp_async16(sbase + doff, src);
        } else {
            *(uint4*)(dsm + doff) = make_uint4(0, 0, 0, 0);
        }
    }
    CP_COMMIT();
    CP_WAIT(0);
    __syncthreads();

    // ---- per-warp: QK mma -> exp/mask -> P frags -> PV mma ----
    const int g   = lane >> 2;
    const int tig = lane & 3;
    const uint32_t loL = sbase + (uint32_t)((lane & 15) * 144 + (lane >> 4) * 16);
    const int i0 = t * 16 + g, i1 = i0 + 8;
    const int jgbase = r0 * 16;

    // hoist Q fragments (one 16x64 tile per warp, reused for all partitions)
    uint32_t qa[4][4];
#pragma unroll
    for (int ks = 0; ks < 4; ks++)
        ldmx4(qa[ks], loL + A_OFF_Q + ks * 32);

    float oacc[8][4];
#pragma unroll
    for (int dt = 0; dt < 8; dt++)
#pragma unroll
        for (int j = 0; j < 4; j++) oacc[dt][j] = 0.f;
    float rs0 = 0.f, rs1 = 0.f;

    const int np = (wid == 7) ? 3 : 2;
    for (int pi = 0; pi < np; pi++) {
        const int pr = (pi == 0) ? wid : (pi == 1) ? (wid + 8) : 16;
        float c0[4] = {0.f, 0.f, 0.f, 0.f};
        float c1[4] = {0.f, 0.f, 0.f, 0.f};
#pragma unroll
        for (int ks = 0; ks < 4; ks++) {
            uint32_t kh[4];
            ldmx4(kh, loL + A_OFF_K + (uint32_t)pr * 2304 + ks * 32);
            mma16816h(c0, qa[ks], kh[0], kh[2]);
            mma16816h(c1, qa[ks], kh[1], kh[3]);
        }
        uint32_t pf[4];
#pragma unroll
        for (int s = 0; s < 2; s++) {
            const float* cc = s ? c1 : c0;
            const int jg0 = jgbase + pr * 16 + s * 8 + 2 * tig;
            const int jg1 = jg0 + 1;
            const bool ok0 = (jg0 >= 0) && (jg0 < S_LEN);
            const bool ok1 = (jg1 >= 0) && (jg1 < S_LEN);
            float w00 = (ok0 && jg0 >= i0 - WWIN && jg0 < i0 + WWIN)
                        ? (__expf(cc[0] * 0.125f) - 1.f) : 0.f;
            float w01 = (ok1 && jg1 >= i0 - WWIN && jg1 < i0 + WWIN)
                        ? (__expf(cc[1] * 0.125f) - 1.f) : 0.f;
            float w10 = (ok0 && jg0 >= i1 - WWIN && jg0 < i1 + WWIN)
                        ? (__expf(cc[2] * 0.125f) - 1.f) : 0.f;
            float w11 = (ok1 && jg1 >= i1 - WWIN && jg1 < i1 + WWIN)
                        ? (__expf(cc[3] * 0.125f) - 1.f) : 0.f;
            rs0 += w00 + w01;
            rs1 += w10 + w11;
            pf[s * 2 + 0] = packh2(w00, w01);
            pf[s * 2 + 1] = packh2(w10, w11);
        }
#pragma unroll
        for (int dp = 0; dp < 4; dp++) {
            uint32_t vb[4];
            ldmx4t(vb, loL + A_OFF_V + (uint32_t)pr * 2304 + dp * 32);
            mma16816h(oacc[dp * 2 + 0], pf, vb[0], vb[1]);
            mma16816h(oacc[dp * 2 + 1], pf, vb[2], vb[3]);
        }
    }

    rs0 += __shfl_xor_sync(0xFFFFFFFF, rs0, 1);
    rs0 += __shfl_xor_sync(0xFFFFFFFF, rs0, 2);
    rs1 += __shfl_xor_sync(0xFFFFFFFF, rs1, 1);
    rs1 += __shfl_xor_sync(0xFFFFFFFF, rs1, 2);
    if (tig == 0) {
        rsp[wid * 16 + g]     = rs0;
        rsp[wid * 16 + g + 8] = rs1;
    }
    __syncthreads();   // all K reads done; op may alias K now

    {
        float* op = (float*)(dsm + A_OFF_OP) + wid * 1024;
#pragma unroll
        for (int dt = 0; dt < 8; dt++) {
            *(float2*)&op[g * 64 + dt * 8 + 2 * tig] =
                make_float2(oacc[dt][0], oacc[dt][1]);
            *(float2*)&op[(g + 8) * 64 + dt * 8 + 2 * tig] =
                make_float2(oacc[dt][2], oacc[dt][3]);
        }
    }
    if (tid < 16) {
        float s = 0.f;
#pragma unroll
        for (int w8 = 0; w8 < 8; w8++) s += rsp[w8 * 16 + tid];
        den[tid] = (float)S_LEN + s;
    }
    __syncthreads();

    {
        const int qi = tid >> 4;
        const int dc = tid & 15;
        const float* opf = (const float*)(dsm + A_OFF_OP);
        float4 sum = *(const float4*)&vt[dc * 4];
#pragma unroll
        for (int w8 = 0; w8 < 8; w8++) {
            const float4 o = *(const float4*)&opf[w8 * 1024 + qi * 64 + dc * 4];
            sum.x += o.x; sum.y += o.y; sum.z += o.z; sum.w += o.w;
        }
        const float inv = 1.0f / den[qi];
        sum.x *= inv; sum.y *= inv; sum.z *= inv; sum.w *= inv;
        const int i = t * 16 + qi;
        *(float4*)&out[((size_t)b * S_LEN + i) * E_DIM + h * HD + dc * 4] = sum;
    }
}

// ============================================================================
// kernel_launch
// ============================================================================
extern "C" void kernel_launch(void* const* d_in, const int* in_sizes, int n_in,
                              void* d_out, int out_size) {
    (void)in_sizes; (void)n_in; (void)out_size;
    const float* x  = (const float*)d_in[0];
    const float* Wq = (const float*)d_in[1];
    const float* bq = (const float*)d_in[2];
    const float* Wk = (const float*)d_in[3];
    const float* bk = (const float*)d_in[4];
    const float* Wv = (const float*)d_in[5];
    const float* bv = (const float*)d_in[6];
    float* out = (float*)d_out;

    split_all_kernel<<<SPLIT_BLOCKS, 256>>>(x, Wq, Wk, Wv);

    cudaFuncSetAttribute(hmma_gemm_kernel, cudaFuncAttributeMaxDynamicSharedMemorySize,
                         GEMM_SMEM);
    dim3 gg(E_DIM / 128, M_TOT / 128, 3);
    hmma_gemm_kernel<<<gg, 256, GEMM_SMEM>>>(bq, bk, bv);

    vtotal_kernel<<<BATCH * NH, 512>>>();

    cudaFuncSetAttribute(attn_tc_kernel, cudaFuncAttributeMaxDynamicSharedMemorySize,
                         A_SMEM);
    dim3 g3(128, NH, BATCH);
    attn_tc_kernel<<<g3, 256, A_SMEM>>>(out);
}

// round 15
// speedup vs baseline: 5.3177x; 1.1057x over previous
#include <cuda_runtime.h>
#include <cuda_fp16.h>
#include <cstdint>

#define S_LEN 2048
#define E_DIM 1024
#define NH    16
#define HD    64
#define WWIN  128
#define BATCH 2
#define M_TOT (BATCH * S_LEN)   // 4096

// ---------------- scratch (device globals; no allocations allowed) ----------------
__device__ float g_Vtot[BATCH * NH * HD];
__device__ __half g_Xh16[M_TOT * E_DIM];
__device__ __half g_Wh16[3 * E_DIM * E_DIM];
__device__ __half g_Q16[M_TOT * E_DIM];
__device__ __half g_K16[M_TOT * E_DIM];
__device__ __half g_V16[M_TOT * E_DIM];

// ---------------- PTX helpers (baseline ISA only) ----------------
__device__ __forceinline__ uint32_t smem_u32(const void* p) {
    uint32_t a;
    asm("{ .reg .u64 t; cvta.to.shared.u64 t, %1; cvt.u32.u64 %0, t; }" : "=r"(a) : "l"(p));
    return a;
}
__device__ __forceinline__ void cp_async16(uint32_t s, const void* g) {
    asm volatile("cp.async.cg.shared.global [%0], [%1], 16;" :: "r"(s), "l"(g) : "memory");
}
#define CP_COMMIT() asm volatile("cp.async.commit_group;" ::: "memory")
#define CP_WAIT(n)  asm volatile("cp.async.wait_group %0;" :: "n"(n) : "memory")

__device__ __forceinline__ void ldmx4(uint32_t r[4], uint32_t addr) {
    asm volatile("ldmatrix.sync.aligned.m8n8.x4.shared.b16 {%0,%1,%2,%3}, [%4];"
                 : "=r"(r[0]), "=r"(r[1]), "=r"(r[2]), "=r"(r[3]) : "r"(addr));
}
__device__ __forceinline__ void ldmx4t(uint32_t r[4], uint32_t addr) {
    asm volatile("ldmatrix.sync.aligned.m8n8.x4.trans.shared.b16 {%0,%1,%2,%3}, [%4];"
                 : "=r"(r[0]), "=r"(r[1]), "=r"(r[2]), "=r"(r[3]) : "r"(addr));
}
__device__ __forceinline__ void mma16816h(float c[4], const uint32_t a[4],
                                          uint32_t b0, uint32_t b1) {
    asm volatile(
        "mma.sync.aligned.m16n8k16.row.col.f32.f16.f16.f32 "
        "{%0,%1,%2,%3}, {%4,%5,%6,%7}, {%8,%9}, {%0,%1,%2,%3};"
        : "+f"(c[0]), "+f"(c[1]), "+f"(c[2]), "+f"(c[3])
        : "r"(a[0]), "r"(a[1]), "r"(a[2]), "r"(a[3]), "r"(b0), "r"(b1));
}

// ============================================================================
// Kernel 0: merged fp32 -> f16 convert for X, Wq, Wk, Wv + zero g_Vtot.
// ============================================================================
#define XQ (M_TOT * E_DIM / 4)      // 1048576
#define WQ (E_DIM * E_DIM / 4)      // 262144
#define SPLIT_BLOCKS ((XQ + 3 * WQ) / 256)   // 7168

__global__ __launch_bounds__(256, 8)
void split_all_kernel(const float* __restrict__ x, const float* __restrict__ wq,
                      const float* __restrict__ wk, const float* __restrict__ wv) {
    if (blockIdx.x == 0) {   // zero Vtot for this replay (epilogue accumulates)
#pragma unroll
        for (int k = 0; k < 8; k++) g_Vtot[threadIdx.x * 8 + k] = 0.f;
    }
    const int i = blockIdx.x * 256 + threadIdx.x;
    const float* src;
    __half2* dst;
    int k;
    if (i < XQ) {
        src = x; k = i; dst = (__half2*)g_Xh16;
    } else {
        const int j = i - XQ;
        const int w = j / WQ;
        k = j - w * WQ;
        src = (w == 0) ? wq : (w == 1) ? wk : wv;
        dst = (__half2*)(g_Wh16 + (size_t)w * E_DIM * E_DIM);
    }
    float4 v = ((const float4*)src)[k];
    dst[2 * k]     = __floats2half2_rn(v.x, v.y);
    dst[2 * k + 1] = __floats2half2_rn(v.z, v.w);
}

// ============================================================================
// Kernel 1: single-product f16 GEMM via mma.sync.
//   Out = X16 @ W16.T + b.  Epilogue writes f16; for V also reduces the
//   rounded outputs over rows into g_Vtot (each CTA owns one (b,h) slab).
// ============================================================================
#define KC 64
#define NCHUNK (E_DIM / KC)
#define RS 144
#define T_A 0
#define T_B 18432
#define STAGE 36864
#define GEMM_SMEM (2 * STAGE)   // 73728 -> 2 CTAs/SM

__device__ __forceinline__ void issue_chunk(uint32_t sdst, int kc, int m0, int n0,
                                            const __half* Wh, int tid) {
#pragma unroll
    for (int t4 = 0; t4 < 4; t4++) {
        const int idx = tid + t4 * 256;
        const int r = idx >> 3, c = idx & 7;
        const uint32_t so = (uint32_t)(r * RS + c * 16);
        cp_async16(sdst + T_A + so,
                   g_Xh16 + (size_t)(m0 + r) * E_DIM + kc * KC + c * 8);
        cp_async16(sdst + T_B + so,
                   Wh + (size_t)(n0 + r) * E_DIM + kc * KC + c * 8);
    }
}

__global__ __launch_bounds__(256, 2)
void hmma_gemm_kernel(const float* __restrict__ bq, const float* __restrict__ bk,
                      const float* __restrict__ bv) {
    extern __shared__ char dsm[];
    const uint32_t sbase = smem_u32(dsm);
    const int tid  = threadIdx.x;
    const int wid  = tid >> 5;
    const int lane = tid & 31;
    const int n0 = blockIdx.x * 128;
    const int m0 = blockIdx.y * 128;
    const int z  = blockIdx.z;

    const __half* Wh = g_Wh16 + (size_t)z * E_DIM * E_DIM;
    const float* bias = (z == 0) ? bq : (z == 1) ? bk : bv;

    const int wm = wid & 1;
    const int wn = wid >> 1;

    float acc[4][4][4];
#pragma unroll
    for (int mt = 0; mt < 4; mt++)
#pragma unroll
        for (int nt = 0; nt < 4; nt++)
#pragma unroll
            for (int j = 0; j < 4; j++) acc[mt][nt][j] = 0.f;

    const uint32_t laneOff = (uint32_t)((lane & 15) * RS + (lane >> 4) * 16);

    issue_chunk(sbase, 0, m0, n0, Wh, tid);
    CP_COMMIT();

    for (int c = 0; c < NCHUNK; c++) {
        const uint32_t sbuf = sbase + (uint32_t)(c & 1) * STAGE;
        if (c + 1 < NCHUNK) {
            issue_chunk(sbase + (uint32_t)((c + 1) & 1) * STAGE, c + 1, m0, n0, Wh, tid);
            CP_COMMIT();
            CP_WAIT(1);
        } else {
            CP_WAIT(0);
        }
        __syncthreads();

        const uint32_t sA = sbuf + T_A + (uint32_t)(wm * 64) * RS + laneOff;
        const uint32_t sB = sbuf + T_B + (uint32_t)(wn * 32) * RS + laneOff;
#pragma unroll
        for (int ks = 0; ks < 4; ks++) {
            uint32_t bfr[2][4];
#pragma unroll
            for (int p = 0; p < 2; p++)
                ldmx4(bfr[p], sB + (uint32_t)(p * 16) * RS + ks * 32);
#pragma unroll
            for (int mt = 0; mt < 4; mt++) {
                uint32_t a[4];
                ldmx4(a, sA + (uint32_t)(mt * 16) * RS + ks * 32);
#pragma unroll
                for (int nt = 0; nt < 4; nt++) {
                    const int p = nt >> 1, s = nt & 1;
                    mma16816h(acc[mt][nt], a, bfr[p][s], bfr[p][s + 2]);
                }
            }
        }
        __syncthreads();
    }

    // epilogue: +bias, write f16; V also accumulates column sums (rounded vals)
    const int g   = lane >> 2;
    const int tig = lane & 3;
    __half* Oh = (z == 0) ? g_Q16 : (z == 1) ? g_K16 : g_V16;
    float vs0[4] = {0.f, 0.f, 0.f, 0.f};   // per-nt sums of col ncol
    float vs1[4] = {0.f, 0.f, 0.f, 0.f};   // per-nt sums of col ncol+1
#pragma unroll
    for (int mt = 0; mt < 4; mt++) {
        const int rbase = m0 + wm * 64 + mt * 16 + g;
#pragma unroll
        for (int nt = 0; nt < 4; nt++) {
            const int ncol = n0 + wn * 32 + nt * 8 + tig * 2;
            const float b0 = bias[ncol], b1 = bias[ncol + 1];
            __half2 r0 = __floats2half2_rn(acc[mt][nt][0] + b0, acc[mt][nt][1] + b1);
            __half2 r1 = __floats2half2_rn(acc[mt][nt][2] + b0, acc[mt][nt][3] + b1);
            *(__half2*)&Oh[(size_t)rbase * E_DIM + ncol] = r0;
            *(__half2*)&Oh[(size_t)(rbase + 8) * E_DIM + ncol] = r1;
            if (z == 2) {
                float2 f0 = __half22float2(r0), f1 = __half22float2(r1);
                vs0[nt] += f0.x + f1.x;
                vs1[nt] += f0.y + f1.y;
            }
        }
    }
    if (z == 2) {
        float* vred = (float*)dsm;          // stages no longer needed
        __syncthreads();
        if (tid < 64) vred[tid] = 0.f;
        __syncthreads();
        const int dbase = (wn & 1) * 32 + tig * 2;
#pragma unroll
        for (int nt = 0; nt < 4; nt++) {
            atomicAdd(&vred[dbase + nt * 8], vs0[nt]);
            atomicAdd(&vred[dbase + nt * 8 + 1], vs1[nt]);
        }
        __syncthreads();
        if (tid < 64) atomicAdd(&g_Vtot[(m0 >> 7) * 64 + tid], vred[tid]);
    }
}

// ============================================================================
// Kernel 2: tensor-core windowed attention, 2 query-tiles per CTA.
//   CTA = (t0=2bx, h, b): 32 queries, shared K/V window of 18 rows (288 keys).
//   Warps 0-3 -> tile 0, warps 4-7 -> tile 1; each warp 4-5 of 17 partitions.
//   smem: Q [32][72], K [288][72], V [288][72]  (~87KB, 2 CTAs/SM).
// ============================================================================
#define TB 2
#define A_OFF_VT   0
#define A_OFF_DEN  256
#define A_OFF_RS   384
#define A_OFF_Q    1024
#define A_OFF_K    5632
#define A_OFF_V    47104
#define A_SMEM     88576
#define A_OFF_OP   A_OFF_K     // 32KB partials alias K after last sync

__device__ __forceinline__ uint32_t packh2(float a, float b) {
    __half2 h = __floats2half2_rn(a, b);
    return *(uint32_t*)&h;
}

__global__ __launch_bounds__(256, 2)
void attn_tc_kernel(float* __restrict__ out) {
    extern __shared__ char dsm[];
    const uint32_t sbase = smem_u32(dsm);
    const int t0  = blockIdx.x * TB;
    const int h   = blockIdx.y;
    const int b   = blockIdx.z;
    const int tid = threadIdx.x;
    const int wid = tid >> 5;
    const int lane = tid & 31;

    float* vt  = (float*)(dsm + A_OFF_VT);
    float* den = (float*)(dsm + A_OFF_DEN);
    float* rsp = (float*)(dsm + A_OFF_RS);

    const size_t headrow = (size_t)b * S_LEN + (size_t)h * 128;

    // ---- load phase: pure cp.async ----
    {   // Q: 2 rows = 256 x 16B units
        const int qi = tid >> 3, c = tid & 7;
        cp_async16(sbase + A_OFF_Q + (uint32_t)(qi * 144 + c * 16),
                   g_Q16 + (headrow + t0 + (qi >> 4)) * E_DIM + (qi & 15) * 64 + c * 8);
    }
    if (tid < 64) vt[tid] = g_Vtot[((b * NH) + h) * HD + tid];

    const int r0 = t0 - 8;
#pragma unroll 6
    for (int rro = 0; rro < 18; rro++) {
        const int rr = r0 + rro;
        const bool ok = (rr >= 0 && rr < 128);
        const int half = tid >> 7;          // 0: K, 1: V
        const int jl16 = (tid >> 3) & 15, c = tid & 7;
        const uint32_t doff = (half ? A_OFF_V : A_OFF_K) +
                              (uint32_t)((rro * 16 + jl16) * 144 + c * 16);
        if (ok) {
            const __half* src = (half ? g_V16 : g_K16) +
                                (headrow + rr) * E_DIM + jl16 * 64 + c * 8;
            cp_async16(sbase + doff, src);
        } else {
            *(uint4*)(dsm + doff) = make_uint4(0, 0, 0, 0);
        }
    }
    CP_COMMIT();
    CP_WAIT(0);
    __syncthreads();

    // ---- per-warp: QK mma -> exp/mask -> P frags -> PV mma ----
    const int tile = wid >> 2;
    const int wt   = wid & 3;
    const int g    = lane >> 2;
    const int tig  = lane & 3;
    const uint32_t loL = sbase + (uint32_t)((lane & 15) * 144 + (lane >> 4) * 16);
    const int i0 = (t0 + tile) * 16 + g, i1 = i0 + 8;

    // hoist Q fragments for this warp's tile
    uint32_t qa[4][4];
#pragma unroll
    for (int ks = 0; ks < 4; ks++)
        ldmx4(qa[ks], loL + A_OFF_Q + (uint32_t)tile * 2304 + ks * 32);

    float oacc[8][4];
#pragma unroll
    for (int dt = 0; dt < 8; dt++)
#pragma unroll
        for (int j = 0; j < 4; j++) oacc[dt][j] = 0.f;
    float rs0 = 0.f, rs1 = 0.f;

    for (int pr = wt; pr < 17; pr += 4) {
        const uint32_t kvOff = (uint32_t)(tile + pr) * 2304;
        const int jgb = (r0 + tile + pr) * 16;
        float c0[4] = {0.f, 0.f, 0.f, 0.f};
        float c1[4] = {0.f, 0.f, 0.f, 0.f};
#pragma unroll
        for (int ks = 0; ks < 4; ks++) {
            uint32_t kh[4];
            ldmx4(kh, loL + A_OFF_K + kvOff + ks * 32);
            mma16816h(c0, qa[ks], kh[0], kh[2]);
            mma16816h(c1, qa[ks], kh[1], kh[3]);
        }
        uint32_t pf[4];
#pragma unroll
        for (int s = 0; s < 2; s++) {
            const float* cc = s ? c1 : c0;
            const int jg0 = jgb + s * 8 + 2 * tig;
            const int jg1 = jg0 + 1;
            const bool ok0 = (jg0 >= 0) && (jg0 < S_LEN);
            const bool ok1 = (jg1 >= 0) && (jg1 < S_LEN);
            float w00 = (ok0 && jg0 >= i0 - WWIN && jg0 < i0 + WWIN)
                        ? (__expf(cc[0] * 0.125f) - 1.f) : 0.f;
            float w01 = (ok1 && jg1 >= i0 - WWIN && jg1 < i0 + WWIN)
                        ? (__expf(cc[1] * 0.125f) - 1.f) : 0.f;
            float w10 = (ok0 && jg0 >= i1 - WWIN && jg0 < i1 + WWIN)
                        ? (__expf(cc[2] * 0.125f) - 1.f) : 0.f;
            float w11 = (ok1 && jg1 >= i1 - WWIN && jg1 < i1 + WWIN)
                        ? (__expf(cc[3] * 0.125f) - 1.f) : 0.f;
            rs0 += w00 + w01;
            rs1 += w10 + w11;
            pf[s * 2 + 0] = packh2(w00, w01);
            pf[s * 2 + 1] = packh2(w10, w11);
        }
#pragma unroll
        for (int dp = 0; dp < 4; dp++) {
            uint32_t vb[4];
            ldmx4t(vb, loL + A_OFF_V + kvOff + dp * 32);
            mma16816h(oacc[dp * 2 + 0], pf, vb[0], vb[1]);
            mma16816h(oacc[dp * 2 + 1], pf, vb[2], vb[3]);
        }
    }

    rs0 += __shfl_xor_sync(0xFFFFFFFF, rs0, 1);
    rs0 += __shfl_xor_sync(0xFFFFFFFF, rs0, 2);
    rs1 += __shfl_xor_sync(0xFFFFFFFF, rs1, 1);
    rs1 += __shfl_xor_sync(0xFFFFFFFF, rs1, 2);
    if (tig == 0) {
        rsp[tile * 64 + wt * 16 + g]     = rs0;
        rsp[tile * 64 + wt * 16 + g + 8] = rs1;
    }
    __syncthreads();   // all K/V reads done; op may alias K now

    {
        float* op = (float*)(dsm + A_OFF_OP) + (tile * 4 + wt) * 1024;
#pragma unroll
        for (int dt = 0; dt < 8; dt++) {
            *(float2*)&op[g * 64 + dt * 8 + 2 * tig] =
                make_float2(oacc[dt][0], oacc[dt][1]);
            *(float2*)&op[(g + 8) * 64 + dt * 8 + 2 * tig] =
                make_float2(oacc[dt][2], oacc[dt][3]);
        }
    }
    if (tid < 32) {
        float s = 0.f;
#pragma unroll
        for (int w4 = 0; w4 < 4; w4++)
            s += rsp[(tid >> 4) * 64 + w4 * 16 + (tid & 15)];
        den[tid] = (float)S_LEN + s;
    }
    __syncthreads();

    {
        const int qi = tid >> 3;         // 0..31 (tile*16 + q)
        const int d0 = (tid & 7) * 8;
        const float* opf = (const float*)(dsm + A_OFF_OP);
        float4 s0 = *(const float4*)&vt[d0];
        float4 s1 = *(const float4*)&vt[d0 + 4];
#pragma unroll
        for (int w4 = 0; w4 < 4; w4++) {
            const float* op = &opf[(((qi >> 4) * 4 + w4) * 16 + (qi & 15)) * 64];
            const float4 a0 = *(const float4*)&op[d0];
            const float4 a1 = *(const float4*)&op[d0 + 4];
            s0.x += a0.x; s0.y += a0.y; s0.z += a0.z; s0.w += a0.w;
            s1.x += a1.x; s1.y += a1.y; s1.z += a1.z; s1.w += a1.w;
        }
        const float inv = 1.0f / den[qi];
        s0.x *= inv; s0.y *= inv; s0.z *= inv; s0.w *= inv;
        s1.x *= inv; s1.y *= inv; s1.z *= inv; s1.w *= inv;
        const int i = (t0 + (qi >> 4)) * 16 + (qi & 15);
        float* orow = &out[((size_t)b * S_LEN + i) * E_DIM + h * HD + d0];
        *(float4*)orow = s0;
        *(float4*)(orow + 4) = s1;
    }
}

// ============================================================================
// kernel_launch
// ============================================================================
extern "C" void kernel_launch(void* const* d_in, const int* in_sizes, int n_in,
                              void* d_out, int out_size) {
    (void)in_sizes; (void)n_in; (void)out_size;
    const float* x  = (const float*)d_in[0];
    const float* Wq = (const float*)d_in[1];
    const float* bq = (const float*)d_in[2];
    const float* Wk = (const float*)d_in[3];
    const float* bk = (const float*)d_in[4];
    const float* Wv = (const float*)d_in[5];
    const float* bv = (const float*)d_in[6];
    float* out = (float*)d_out;

    split_all_kernel<<<SPLIT_BLOCKS, 256>>>(x, Wq, Wk, Wv);

    cudaFuncSetAttribute(hmma_gemm_kernel, cudaFuncAttributeMaxDynamicSharedMemorySize,
                         GEMM_SMEM);
    dim3 gg(E_DIM / 128, M_TOT / 128, 3);
    hmma_gemm_kernel<<<gg, 256, GEMM_SMEM>>>(bq, bk, bv);

    cudaFuncSetAttribute(attn_tc_kernel, cudaFuncAttributeMaxDynamicSharedMemorySize,
                         A_SMEM);
    dim3 g3(S_LEN / (16 * TB), NH, BATCH);   // (64, 16, 2)
    attn_tc_kernel<<<g3, 256, A_SMEM>>>(out);
}

// round 16
// speedup vs baseline: 5.7543x; 1.0821x over previous
#include <cuda_runtime.h>
#include <cuda_fp16.h>
#include <cstdint>

#define S_LEN 2048
#define E_DIM 1024
#define NH    16
#define HD    64
#define WWIN  128
#define BATCH 2
#define M_TOT (BATCH * S_LEN)   // 4096

// ---------------- scratch (device globals; no allocations allowed) ----------------
__device__ float g_Vtot[BATCH * NH * HD];
__device__ __half g_Xh16[M_TOT * E_DIM];
__device__ __half g_Wh16[3 * E_DIM * E_DIM];
__device__ __half g_Q16[M_TOT * E_DIM];
__device__ __half g_K16[M_TOT * E_DIM];
__device__ __half g_V16[M_TOT * E_DIM];

// ---------------- PTX helpers (baseline ISA only) ----------------
__device__ __forceinline__ uint32_t smem_u32(const void* p) {
    uint32_t a;
    asm("{ .reg .u64 t; cvta.to.shared.u64 t, %1; cvt.u32.u64 %0, t; }" : "=r"(a) : "l"(p));
    return a;
}
__device__ __forceinline__ void cp_async16(uint32_t s, const void* g) {
    asm volatile("cp.async.cg.shared.global [%0], [%1], 16;" :: "r"(s), "l"(g) : "memory");
}
#define CP_COMMIT() asm volatile("cp.async.commit_group;" ::: "memory")
#define CP_WAIT(n)  asm volatile("cp.async.wait_group %0;" :: "n"(n) : "memory")

__device__ __forceinline__ void ldmx4(uint32_t r[4], uint32_t addr) {
    asm volatile("ldmatrix.sync.aligned.m8n8.x4.shared.b16 {%0,%1,%2,%3}, [%4];"
                 : "=r"(r[0]), "=r"(r[1]), "=r"(r[2]), "=r"(r[3]) : "r"(addr));
}
__device__ __forceinline__ void ldmx4t(uint32_t r[4], uint32_t addr) {
    asm volatile("ldmatrix.sync.aligned.m8n8.x4.trans.shared.b16 {%0,%1,%2,%3}, [%4];"
                 : "=r"(r[0]), "=r"(r[1]), "=r"(r[2]), "=r"(r[3]) : "r"(addr));
}
__device__ __forceinline__ void mma16816h(float c[4], const uint32_t a[4],
                                          uint32_t b0, uint32_t b1) {
    asm volatile(
        "mma.sync.aligned.m16n8k16.row.col.f32.f16.f16.f32 "
        "{%0,%1,%2,%3}, {%4,%5,%6,%7}, {%8,%9}, {%0,%1,%2,%3};"
        : "+f"(c[0]), "+f"(c[1]), "+f"(c[2]), "+f"(c[3])
        : "r"(a[0]), "r"(a[1]), "r"(a[2]), "r"(a[3]), "r"(b0), "r"(b1));
}

// ============================================================================
// Kernel 0: merged fp32 -> f16 convert for X, Wq, Wk, Wv + zero g_Vtot.
// ============================================================================
#define XQ (M_TOT * E_DIM / 4)      // 1048576
#define WQ (E_DIM * E_DIM / 4)      // 262144
#define SPLIT_BLOCKS ((XQ + 3 * WQ) / 256)   // 7168

__global__ __launch_bounds__(256, 8)
void split_all_kernel(const float* __restrict__ x, const float* __restrict__ wq,
                      const float* __restrict__ wk, const float* __restrict__ wv) {
    if (blockIdx.x == 0) {   // zero Vtot for this replay (epilogue accumulates)
#pragma unroll
        for (int k = 0; k < 8; k++) g_Vtot[threadIdx.x * 8 + k] = 0.f;
    }
    const int i = blockIdx.x * 256 + threadIdx.x;
    const float* src;
    __half2* dst;
    int k;
    if (i < XQ) {
        src = x; k = i; dst = (__half2*)g_Xh16;
    } else {
        const int j = i - XQ;
        const int w = j / WQ;
        k = j - w * WQ;
        src = (w == 0) ? wq : (w == 1) ? wk : wv;
        dst = (__half2*)(g_Wh16 + (size_t)w * E_DIM * E_DIM);
    }
    float4 v = ((const float4*)src)[k];
    dst[2 * k]     = __floats2half2_rn(v.x, v.y);
    dst[2 * k + 1] = __floats2half2_rn(v.z, v.w);
}

// ============================================================================
// Kernel 1: single-product f16 GEMM via mma.sync (unchanged — at HMMA ceiling).
// ============================================================================
#define KC 64
#define NCHUNK (E_DIM / KC)
#define RS 144
#define T_A 0
#define T_B 18432
#define STAGE 36864
#define GEMM_SMEM (2 * STAGE)   // 73728 -> 2 CTAs/SM

__device__ __forceinline__ void issue_chunk(uint32_t sdst, int kc, int m0, int n0,
                                            const __half* Wh, int tid) {
#pragma unroll
    for (int t4 = 0; t4 < 4; t4++) {
        const int idx = tid + t4 * 256;
        const int r = idx >> 3, c = idx & 7;
        const uint32_t so = (uint32_t)(r * RS + c * 16);
        cp_async16(sdst + T_A + so,
                   g_Xh16 + (size_t)(m0 + r) * E_DIM + kc * KC + c * 8);
        cp_async16(sdst + T_B + so,
                   Wh + (size_t)(n0 + r) * E_DIM + kc * KC + c * 8);
    }
}

__global__ __launch_bounds__(256, 2)
void hmma_gemm_kernel(const float* __restrict__ bq, const float* __restrict__ bk,
                      const float* __restrict__ bv) {
    extern __shared__ char dsm[];
    const uint32_t sbase = smem_u32(dsm);
    const int tid  = threadIdx.x;
    const int wid  = tid >> 5;
    const int lane = tid & 31;
    const int n0 = blockIdx.x * 128;
    const int m0 = blockIdx.y * 128;
    const int z  = blockIdx.z;

    const __half* Wh = g_Wh16 + (size_t)z * E_DIM * E_DIM;
    const float* bias = (z == 0) ? bq : (z == 1) ? bk : bv;

    const int wm = wid & 1;
    const int wn = wid >> 1;

    float acc[4][4][4];
#pragma unroll
    for (int mt = 0; mt < 4; mt++)
#pragma unroll
        for (int nt = 0; nt < 4; nt++)
#pragma unroll
            for (int j = 0; j < 4; j++) acc[mt][nt][j] = 0.f;

    const uint32_t laneOff = (uint32_t)((lane & 15) * RS + (lane >> 4) * 16);

    issue_chunk(sbase, 0, m0, n0, Wh, tid);
    CP_COMMIT();

    for (int c = 0; c < NCHUNK; c++) {
        const uint32_t sbuf = sbase + (uint32_t)(c & 1) * STAGE;
        if (c + 1 < NCHUNK) {
            issue_chunk(sbase + (uint32_t)((c + 1) & 1) * STAGE, c + 1, m0, n0, Wh, tid);
            CP_COMMIT();
            CP_WAIT(1);
        } else {
            CP_WAIT(0);
        }
        __syncthreads();

        const uint32_t sA = sbuf + T_A + (uint32_t)(wm * 64) * RS + laneOff;
        const uint32_t sB = sbuf + T_B + (uint32_t)(wn * 32) * RS + laneOff;
#pragma unroll
        for (int ks = 0; ks < 4; ks++) {
            uint32_t bfr[2][4];
#pragma unroll
            for (int p = 0; p < 2; p++)
                ldmx4(bfr[p], sB + (uint32_t)(p * 16) * RS + ks * 32);
#pragma unroll
            for (int mt = 0; mt < 4; mt++) {
                uint32_t a[4];
                ldmx4(a, sA + (uint32_t)(mt * 16) * RS + ks * 32);
#pragma unroll
                for (int nt = 0; nt < 4; nt++) {
                    const int p = nt >> 1, s = nt & 1;
                    mma16816h(acc[mt][nt], a, bfr[p][s], bfr[p][s + 2]);
                }
            }
        }
        __syncthreads();
    }

    // epilogue: +bias, write f16; V also accumulates column sums (rounded vals)
    const int g   = lane >> 2;
    const int tig = lane & 3;
    __half* Oh = (z == 0) ? g_Q16 : (z == 1) ? g_K16 : g_V16;
    float vs0[4] = {0.f, 0.f, 0.f, 0.f};
    float vs1[4] = {0.f, 0.f, 0.f, 0.f};
#pragma unroll
    for (int mt = 0; mt < 4; mt++) {
        const int rbase = m0 + wm * 64 + mt * 16 + g;
#pragma unroll
        for (int nt = 0; nt < 4; nt++) {
            const int ncol = n0 + wn * 32 + nt * 8 + tig * 2;
            const float b0 = bias[ncol], b1 = bias[ncol + 1];
            __half2 r0 = __floats2half2_rn(acc[mt][nt][0] + b0, acc[mt][nt][1] + b1);
            __half2 r1 = __floats2half2_rn(acc[mt][nt][2] + b0, acc[mt][nt][3] + b1);
            *(__half2*)&Oh[(size_t)rbase * E_DIM + ncol] = r0;
            *(__half2*)&Oh[(size_t)(rbase + 8) * E_DIM + ncol] = r1;
            if (z == 2) {
                float2 f0 = __half22float2(r0), f1 = __half22float2(r1);
                vs0[nt] += f0.x + f1.x;
                vs1[nt] += f0.y + f1.y;
            }
        }
    }
    if (z == 2) {
        float* vred = (float*)dsm;
        __syncthreads();
        if (tid < 64) vred[tid] = 0.f;
        __syncthreads();
        const int dbase = (wn & 1) * 32 + tig * 2;
#pragma unroll
        for (int nt = 0; nt < 4; nt++) {
            atomicAdd(&vred[dbase + nt * 8], vs0[nt]);
            atomicAdd(&vred[dbase + nt * 8 + 1], vs1[nt]);
        }
        __syncthreads();
        if (tid < 64) atomicAdd(&g_Vtot[(m0 >> 7) * 64 + tid], vred[tid]);
    }
}

// ============================================================================
// Kernel 2: tensor-core windowed attention, 4 query-tiles per CTA.
//   CTA = (t0=4bx, h, b): 64 queries, shared K/V window of 20 rows (320 keys).
//   2 warps per tile; each warp covers 8-9 of the tile's 17 key-partitions.
//   smem: Q [64][72], K [320][72], V [320][72]  (~100KB, 2 CTAs/SM).
// ============================================================================
#define TB 4
#define A_OFF_VT   0
#define A_OFF_DEN  256
#define A_OFF_RS   512
#define A_OFF_Q    1024
#define A_OFF_K    10240
#define A_OFF_V    56320
#define A_SMEM     102400
#define A_OFF_OP   A_OFF_K     // 8x16x64 f32 = 32KB partials alias K after sync

__device__ __forceinline__ uint32_t packh2(float a, float b) {
    __half2 h = __floats2half2_rn(a, b);
    return *(uint32_t*)&h;
}

__global__ __launch_bounds__(256, 2)
void attn_tc_kernel(float* __restrict__ out) {
    extern __shared__ char dsm[];
    const uint32_t sbase = smem_u32(dsm);
    const int t0  = blockIdx.x * TB;
    const int h   = blockIdx.y;
    const int b   = blockIdx.z;
    const int tid = threadIdx.x;
    const int wid = tid >> 5;
    const int lane = tid & 31;

    float* vt  = (float*)(dsm + A_OFF_VT);
    float* den = (float*)(dsm + A_OFF_DEN);
    float* rsp = (float*)(dsm + A_OFF_RS);

    const size_t headrow = (size_t)b * S_LEN + (size_t)h * 128;

    // ---- load phase: pure cp.async ----
#pragma unroll
    for (int qh = 0; qh < 2; qh++) {   // Q: 4 rows = 512 x 16B units
        const int u = qh * 256 + tid;
        const int qi = u >> 3, c = u & 7;   // qi 0..63
        cp_async16(sbase + A_OFF_Q + (uint32_t)(qi * 144 + c * 16),
                   g_Q16 + (headrow + t0 + (qi >> 4)) * E_DIM + (qi & 15) * 64 + c * 8);
    }
    if (tid < 64) vt[tid] = g_Vtot[((b * NH) + h) * HD + tid];

    const int r0 = t0 - 8;
#pragma unroll 5
    for (int rro = 0; rro < 20; rro++) {
        const int rr = r0 + rro;
        const bool ok = (rr >= 0 && rr < 128);
        const int half = tid >> 7;          // 0: K, 1: V
        const int jl16 = (tid >> 3) & 15, c = tid & 7;
        const uint32_t doff = (half ? A_OFF_V : A_OFF_K) +
                              (uint32_t)((rro * 16 + jl16) * 144 + c * 16);
        if (ok) {
            const __half* src = (half ? g_V16 : g_K16) +
                                (headrow + rr) * E_DIM + jl16 * 64 + c * 8;
            cp_async16(sbase + doff, src);
        } else {
            *(uint4*)(dsm + doff) = make_uint4(0, 0, 0, 0);
        }
    }
    CP_COMMIT();
    CP_WAIT(0);
    __syncthreads();

    // ---- per-warp: QK mma -> exp/mask -> P frags -> PV mma ----
    const int tile  = wid >> 1;      // 0..3
    const int wslot = wid & 1;       // 0..1
    const int g     = lane >> 2;
    const int tig   = lane & 3;
    const uint32_t loL = sbase + (uint32_t)((lane & 15) * 144 + (lane >> 4) * 16);
    const int i0 = (t0 + tile) * 16 + g, i1 = i0 + 8;

    // hoist Q fragments for this warp's tile
    uint32_t qa[4][4];
#pragma unroll
    for (int ks = 0; ks < 4; ks++)
        ldmx4(qa[ks], loL + A_OFF_Q + (uint32_t)tile * 2304 + ks * 32);

    float oacc[8][4];
#pragma unroll
    for (int dt = 0; dt < 8; dt++)
#pragma unroll
        for (int j = 0; j < 4; j++) oacc[dt][j] = 0.f;
    float rs0 = 0.f, rs1 = 0.f;

    for (int pr = wslot; pr < 17; pr += 2) {
        const uint32_t kvOff = (uint32_t)(tile + pr) * 2304;
        const int jgb = (r0 + tile + pr) * 16;
        float c0[4] = {0.f, 0.f, 0.f, 0.f};
        float c1[4] = {0.f, 0.f, 0.f, 0.f};
#pragma unroll
        for (int ks = 0; ks < 4; ks++) {
            uint32_t kh[4];
            ldmx4(kh, loL + A_OFF_K + kvOff + ks * 32);
            mma16816h(c0, qa[ks], kh[0], kh[2]);
            mma16816h(c1, qa[ks], kh[1], kh[3]);
        }
        uint32_t pf[4];
#pragma unroll
        for (int s = 0; s < 2; s++) {
            const float* cc = s ? c1 : c0;
            const int jg0 = jgb + s * 8 + 2 * tig;
            const int jg1 = jg0 + 1;
            const bool ok0 = (jg0 >= 0) && (jg0 < S_LEN);
            const bool ok1 = (jg1 >= 0) && (jg1 < S_LEN);
            float w00 = (ok0 && jg0 >= i0 - WWIN && jg0 < i0 + WWIN)
                        ? (__expf(cc[0] * 0.125f) - 1.f) : 0.f;
            float w01 = (ok1 && jg1 >= i0 - WWIN && jg1 < i0 + WWIN)
                        ? (__expf(cc[1] * 0.125f) - 1.f) : 0.f;
            float w10 = (ok0 && jg0 >= i1 - WWIN && jg0 < i1 + WWIN)
                        ? (__expf(cc[2] * 0.125f) - 1.f) : 0.f;
            float w11 = (ok1 && jg1 >= i1 - WWIN && jg1 < i1 + WWIN)
                        ? (__expf(cc[3] * 0.125f) - 1.f) : 0.f;
            rs0 += w00 + w01;
            rs1 += w10 + w11;
            pf[s * 2 + 0] = packh2(w00, w01);
            pf[s * 2 + 1] = packh2(w10, w11);
        }
#pragma unroll
        for (int dp = 0; dp < 4; dp++) {
            uint32_t vb[4];
            ldmx4t(vb, loL + A_OFF_V + kvOff + dp * 32);
            mma16816h(oacc[dp * 2 + 0], pf, vb[0], vb[1]);
            mma16816h(oacc[dp * 2 + 1], pf, vb[2], vb[3]);
        }
    }

    rs0 += __shfl_xor_sync(0xFFFFFFFF, rs0, 1);
    rs0 += __shfl_xor_sync(0xFFFFFFFF, rs0, 2);
    rs1 += __shfl_xor_sync(0xFFFFFFFF, rs1, 1);
    rs1 += __shfl_xor_sync(0xFFFFFFFF, rs1, 2);
    if (tig == 0) {
        rsp[tile * 32 + wslot * 16 + g]     = rs0;
        rsp[tile * 32 + wslot * 16 + g + 8] = rs1;
    }
    __syncthreads();   // all K/V reads done; op may alias K now

    {
        float* op = (float*)(dsm + A_OFF_OP) + wid * 1024;
#pragma unroll
        for (int dt = 0; dt < 8; dt++) {
            *(float2*)&op[g * 64 + dt * 8 + 2 * tig] =
                make_float2(oacc[dt][0], oacc[dt][1]);
            *(float2*)&op[(g + 8) * 64 + dt * 8 + 2 * tig] =
                make_float2(oacc[dt][2], oacc[dt][3]);
        }
    }
    if (tid < 64) {   // 64 queries
        const int tv = tid >> 4, qr = tid & 15;
        den[tid] = (float)S_LEN + rsp[tv * 32 + qr] + rsp[tv * 32 + 16 + qr];
    }
    __syncthreads();

#pragma unroll
    for (int halfq = 0; halfq < 2; halfq++) {
        const int qv = halfq * 32 + (tid >> 3);   // 0..63
        const int d0 = (tid & 7) * 8;
        const int tv = qv >> 4, qr = qv & 15;
        const float* opf = (const float*)(dsm + A_OFF_OP);
        float4 s0 = *(const float4*)&vt[d0];
        float4 s1 = *(const float4*)&vt[d0 + 4];
#pragma unroll
        for (int w2 = 0; w2 < 2; w2++) {
            const float* op = &opf[((tv * 2 + w2) * 16 + qr) * 64];
            const float4 a0 = *(const float4*)&op[d0];
            const float4 a1 = *(const float4*)&op[d0 + 4];
            s0.x += a0.x; s0.y += a0.y; s0.z += a0.z; s0.w += a0.w;
            s1.x += a1.x; s1.y += a1.y; s1.z += a1.z; s1.w += a1.w;
        }
        const float inv = 1.0f / den[qv];
        s0.x *= inv; s0.y *= inv; s0.z *= inv; s0.w *= inv;
        s1.x *= inv; s1.y *= inv; s1.z *= inv; s1.w *= inv;
        const int i = (t0 + tv) * 16 + qr;
        float* orow = &out[((size_t)b * S_LEN + i) * E_DIM + h * HD + d0];
        *(float4*)orow = s0;
        *(float4*)(orow + 4) = s1;
    }
}

// ============================================================================
// kernel_launch
// ============================================================================
extern "C" void kernel_launch(void* const* d_in, const int* in_sizes, int n_in,
                              void* d_out, int out_size) {
    (void)in_sizes; (void)n_in; (void)out_size;
    const float* x  = (const float*)d_in[0];
    const float* Wq = (const float*)d_in[1];
    const float* bq = (const float*)d_in[2];
    const float* Wk = (const float*)d_in[3];
    const float* bk = (const float*)d_in[4];
    const float* Wv = (const float*)d_in[5];
    const float* bv = (const float*)d_in[6];
    float* out = (float*)d_out;

    split_all_kernel<<<SPLIT_BLOCKS, 256>>>(x, Wq, Wk, Wv);

    cudaFuncSetAttribute(hmma_gemm_kernel, cudaFuncAttributeMaxDynamicSharedMemorySize,
                         GEMM_SMEM);
    dim3 gg(E_DIM / 128, M_TOT / 128, 3);
    hmma_gemm_kernel<<<gg, 256, GEMM_SMEM>>>(bq, bk, bv);

    cudaFuncSetAttribute(attn_tc_kernel, cudaFuncAttributeMaxDynamicSharedMemorySize,
                         A_SMEM);
    dim3 g3(S_LEN / (16 * TB), NH, BATCH);   // (32, 16, 2)
    attn_tc_kernel<<<g3, 256, A_SMEM>>>(out);
}